// round 1
// baseline (speedup 1.0000x reference)
#include <cuda_runtime.h>
#include <cstdint>
#include <math.h>

// ---------------- problem constants ----------------
#define HF 100
#define WF 160
#define NPIX (HF*WF)          // 16000
#define CIN 512
#define COC 512
#define NA 9
#define NROW (NPIX*NA)        // 144000
#define PRE_NMS 6000
#define POST_NMS 300
#define IMG_H 1600.0f
#define IMG_W 2560.0f
#define IOU_THR 0.7f
#define CAND_CAP 16384

// ---------------- scratch (device globals; no cudaMalloc allowed) ----------------
__device__ float               g_Y[NPIX*COC];       // conv output (relu'd)
__device__ float4              g_props[NROW];       // clipped proposals y1,x1,y2,x2
__device__ unsigned long long  g_keys[NROW];
__device__ unsigned int        g_hist[65536];
__device__ unsigned int        g_T;
__device__ unsigned long long  g_cand[CAND_CAP];
__device__ int                 g_cnt;
__device__ int                 g_rows[PRE_NMS];

// ---------------- zero counters ----------------
__global__ void zero_kernel() {
    int i = blockIdx.x * blockDim.x + threadIdx.x;
    if (i < 65536) g_hist[i] = 0u;
    if (i == 0) g_cnt = 0;
}

// ---------------- conv 3x3 (implicit GEMM, 128x128x16 tile, 8x8 per thread) ----------------
__global__ __launch_bounds__(256) void conv_kernel(
    const float* __restrict__ X,   // [100][160][512]
    const float* __restrict__ W1,  // [3][3][512][512]
    const float* __restrict__ b1)  // [512]
{
    __shared__ float As[16*128];
    __shared__ float Bs[16*128];

    int tid = threadIdx.x;
    int bn = blockIdx.x;   // 0..3   (out channels)
    int bm = blockIdx.y;   // 0..124 (pixels)

    int tx = tid & 15, ty = tid >> 4;

    // A-load thread mapping (precompute pixel coords; m = f%128, kk4 = f/128)
    int m_a[2], kk4_a[2], py_a[2], px_a[2];
    #pragma unroll
    for (int i = 0; i < 2; i++) {
        int f = tid + 256*i;
        m_a[i]   = f & 127;
        kk4_a[i] = f >> 7;        // 0..3
        int pix  = bm*128 + m_a[i];
        py_a[i]  = pix / WF;
        px_a[i]  = pix % WF;
    }

    float acc[8][8];
    #pragma unroll
    for (int a = 0; a < 8; a++)
        #pragma unroll
        for (int b = 0; b < 8; b++) acc[a][b] = 0.f;

    for (int kc = 0; kc < 288; kc++) {
        int kbase = kc * 16;
        int sec = kbase >> 9;        // 0..8 tap
        int cb  = kbase & 511;       // channel base
        int ky = sec / 3 - 1, kx = sec % 3 - 1;

        // A tile: 128 pixels x 16 channels
        #pragma unroll
        for (int i = 0; i < 2; i++) {
            int iy = py_a[i] + ky, ix = px_a[i] + kx;
            float4 v = make_float4(0.f,0.f,0.f,0.f);
            if (iy >= 0 && iy < HF && ix >= 0 && ix < WF)
                v = *(const float4*)&X[((size_t)(iy*WF + ix))*CIN + cb + kk4_a[i]*4];
            int base = kk4_a[i]*4;
            int m = m_a[i];
            As[(base+0)*128 + m] = v.x;
            As[(base+1)*128 + m] = v.y;
            As[(base+2)*128 + m] = v.z;
            As[(base+3)*128 + m] = v.w;
        }
        // B tile: 16 k-rows x 128 oc
        #pragma unroll
        for (int i = 0; i < 2; i++) {
            int f = tid + 256*i;
            int oc4 = f & 31, kk = f >> 5;
            float4 v = *(const float4*)&W1[((size_t)(kbase + kk))*COC + bn*128 + oc4*4];
            *(float4*)&Bs[kk*128 + oc4*4] = v;
        }
        __syncthreads();

        #pragma unroll
        for (int kk = 0; kk < 16; kk++) {
            float4 a0 = *(float4*)&As[kk*128 + ty*4];
            float4 a1 = *(float4*)&As[kk*128 + 64 + ty*4];
            float4 b0 = *(float4*)&Bs[kk*128 + tx*4];
            float4 b1v= *(float4*)&Bs[kk*128 + 64 + tx*4];
            float ar[8] = {a0.x,a0.y,a0.z,a0.w,a1.x,a1.y,a1.z,a1.w};
            float br_[8] = {b0.x,b0.y,b0.z,b0.w,b1v.x,b1v.y,b1v.z,b1v.w};
            #pragma unroll
            for (int mi = 0; mi < 8; mi++)
                #pragma unroll
                for (int ni = 0; ni < 8; ni++)
                    acc[mi][ni] += ar[mi] * br_[ni];
        }
        __syncthreads();
    }

    // epilogue: +bias, relu, store
    const float* bp = b1 + bn*128;
    float bias[8];
    #pragma unroll
    for (int u = 0; u < 4; u++) { bias[u] = bp[tx*4+u]; bias[4+u] = bp[64+tx*4+u]; }

    #pragma unroll
    for (int mi = 0; mi < 8; mi++) {
        int m = (mi < 4) ? (ty*4 + mi) : (64 + ty*4 + (mi-4));
        float* yr = g_Y + ((size_t)(bm*128 + m))*COC + bn*128;
        float4 v0, v1;
        v0.x = fmaxf(acc[mi][0]+bias[0],0.f); v0.y = fmaxf(acc[mi][1]+bias[1],0.f);
        v0.z = fmaxf(acc[mi][2]+bias[2],0.f); v0.w = fmaxf(acc[mi][3]+bias[3],0.f);
        v1.x = fmaxf(acc[mi][4]+bias[4],0.f); v1.y = fmaxf(acc[mi][5]+bias[5],0.f);
        v1.z = fmaxf(acc[mi][6]+bias[6],0.f); v1.w = fmaxf(acc[mi][7]+bias[7],0.f);
        *(float4*)&yr[tx*4]      = v0;
        *(float4*)&yr[64+tx*4]   = v1;
    }
}

// ---------------- heads: 1x1 convs + softmax + decode + keys + hist ----------------
__global__ __launch_bounds__(256) void heads_kernel(
    const float* __restrict__ Wc, const float* __restrict__ bc,
    const float* __restrict__ Wr, const float* __restrict__ br,
    const float* __restrict__ anch,
    float* __restrict__ out_scores, float* __restrict__ out_deltas)
{
    extern __shared__ float sW[];   // [512][45]: [0..8]=Wc, [9..44]=Wr
    int tid = threadIdx.x;
    for (int i = tid; i < 512*9;  i += blockDim.x) { int c = i/9;  int o = i%9;  sW[c*45 + o]     = Wc[i]; }
    for (int i = tid; i < 512*36; i += blockDim.x) { int c = i/36; int o = i%36; sW[c*45 + 9 + o] = Wr[i]; }
    __syncthreads();

    int warp = tid >> 5, lane = tid & 31;

    for (int it = 0; it < 8; it++) {
        int pix = blockIdx.x*64 + warp*8 + it;
        const float* yrow = g_Y + (size_t)pix*COC;

        float acc[45];
        #pragma unroll
        for (int o = 0; o < 45; o++) acc[o] = 0.f;

        #pragma unroll
        for (int i = 0; i < 16; i++) {
            int c = lane + 32*i;
            float yv = yrow[c];
            const float* w = &sW[c*45];
            #pragma unroll
            for (int o = 0; o < 45; o++) acc[o] += yv * w[o];
        }
        #pragma unroll
        for (int o = 0; o < 45; o++) {
            float v = acc[o];
            v += __shfl_xor_sync(0xffffffffu, v, 16);
            v += __shfl_xor_sync(0xffffffffu, v, 8);
            v += __shfl_xor_sync(0xffffffffu, v, 4);
            v += __shfl_xor_sync(0xffffffffu, v, 2);
            v += __shfl_xor_sync(0xffffffffu, v, 1);
            acc[o] = v;
        }

        if (lane < 9) {
            int a = lane;
            int r = pix*9 + a;
            float lg[9];
            #pragma unroll
            for (int o = 0; o < 9; o++) lg[o] = acc[o] + bc[o];
            float mx = lg[0];
            #pragma unroll
            for (int o = 1; o < 9; o++) mx = fmaxf(mx, lg[o]);
            float den = 0.f;
            #pragma unroll
            for (int o = 0; o < 9; o++) den += expf(lg[o] - mx);
            float score = expf(lg[a] - mx) / den;
            out_scores[r] = score;

            float d0 = acc[9 + 4*a + 0] + br[4*a + 0];
            float d1 = acc[9 + 4*a + 1] + br[4*a + 1];
            float d2 = acc[9 + 4*a + 2] + br[4*a + 2];
            float d3 = acc[9 + 4*a + 3] + br[4*a + 3];
            out_deltas[(size_t)r*4 + 0] = d0;
            out_deltas[(size_t)r*4 + 1] = d1;
            out_deltas[(size_t)r*4 + 2] = d2;
            out_deltas[(size_t)r*4 + 3] = d3;

            float4 an = ((const float4*)anch)[r];   // cy,cx,h,w
            float cy = an.x + d0*an.z;
            float cx = an.y + d1*an.w;
            float sy = an.z * expf(d2);
            float sx = an.w * expf(d3);
            float y1 = fmaxf(cy - 0.5f*sy, 0.f);
            float x1 = fmaxf(cx - 0.5f*sx, 0.f);
            float y2 = fminf(cy + 0.5f*sy, IMG_H);
            float x2 = fminf(cx + 0.5f*sx, IMG_W);
            g_props[r] = make_float4(y1, x1, y2, x2);

            unsigned sb = __float_as_uint(score);   // positive floats: monotone as uint
            g_keys[r] = ((unsigned long long)sb << 32) | (0xFFFFFFFFu - (unsigned)r);
            atomicAdd(&g_hist[sb >> 16], 1u);
        }
    }
}

// ---------------- threshold bin so that count(bin >= T) >= PRE_NMS ----------------
__global__ void thresh_kernel() {
    __shared__ unsigned int csum[1024];
    int t = threadIdx.x;
    int hi = 65535 - t*64;
    unsigned s = 0;
    for (int b = 0; b < 64; b++) s += g_hist[hi - b];
    csum[t] = s;
    __syncthreads();
    if (t == 0) {
        unsigned cum = 0; unsigned T = 0; bool found = false;
        for (int i = 0; i < 1024 && !found; i++) {
            if (cum + csum[i] >= PRE_NMS) {
                int hb = 65535 - i*64;
                for (int b = 0; b < 64; b++) {
                    cum += g_hist[hb - b];
                    if (cum >= PRE_NMS) { T = (unsigned)(hb - b); found = true; break; }
                }
            } else cum += csum[i];
        }
        g_T = T;   // T=0 if total < PRE_NMS (cannot happen: 144000 >= 6000)
    }
}

// ---------------- compact candidates with bin >= T ----------------
__global__ void compact_kernel() {
    int r = blockIdx.x*blockDim.x + threadIdx.x;
    if (r >= NROW) return;
    unsigned long long k = g_keys[r];
    if ((unsigned)(k >> 48) >= g_T) {
        int p = atomicAdd(&g_cnt, 1);
        if (p < CAND_CAP) g_cand[p] = k;
    }
}

// ---------------- one-block bitonic sort (descending), output sorted rows ----------------
__global__ __launch_bounds__(1024) void sort_kernel() {
    extern __shared__ unsigned long long sk[];   // 16384 * 8 = 128 KB
    int n = g_cnt; if (n > CAND_CAP) n = CAND_CAP;
    for (int i = threadIdx.x; i < CAND_CAP; i += 1024)
        sk[i] = (i < n) ? g_cand[i] : 0ULL;
    __syncthreads();

    for (int k = 2; k <= CAND_CAP; k <<= 1) {
        for (int j = k >> 1; j > 0; j >>= 1) {
            for (int i = threadIdx.x; i < CAND_CAP; i += 1024) {
                int ixj = i ^ j;
                if (ixj > i) {
                    unsigned long long a = sk[i], b = sk[ixj];
                    bool descBlock = ((i & k) == 0);
                    bool doSwap = descBlock ? (a < b) : (a > b);
                    if (doSwap) { sk[i] = b; sk[ixj] = a; }
                }
            }
            __syncthreads();
        }
    }
    for (int i = threadIdx.x; i < PRE_NMS; i += 1024)
        g_rows[i] = (int)(0xFFFFFFFFu - (unsigned)(sk[i] & 0xFFFFFFFFULL));
}

// ---------------- greedy NMS on sorted list (equivalent to reference scan) ----------------
__global__ __launch_bounds__(256) void nms_kernel(float* __restrict__ out_props) {
    extern __shared__ unsigned char smem[];
    float4* box  = (float4*)smem;                       // 6000 * 16 = 96000 B
    float*  ky1  = (float*)(smem + 96000);              // 300
    float*  kx1  = ky1 + POST_NMS;
    float*  ky2  = kx1 + POST_NMS;
    float*  kx2  = ky2 + POST_NMS;
    float*  karea= kx2 + POST_NMS;
    __shared__ int s_nk;

    int tid = threadIdx.x;
    for (int i = tid; i < PRE_NMS; i += blockDim.x)
        box[i] = g_props[g_rows[i]];
    __syncthreads();

    if (tid < 32) {
        int lane = tid;
        int nk = 0;
        for (int i = 0; i < PRE_NMS && nk < POST_NMS; i++) {
            float4 b = box[i];
            float h = b.z - b.x, w = b.w - b.y;
            if (h < 16.f || w < 16.f) continue;       // invalid -> score=NEG, never selected
            float area = h * w;
            bool sup = false;
            for (int j0 = 0; j0 < nk; j0 += 32) {
                int j = j0 + lane;
                bool p = false;
                if (j < nk) {
                    float iy1 = fmaxf(ky1[j], b.x);
                    float ix1 = fmaxf(kx1[j], b.y);
                    float iy2 = fminf(ky2[j], b.z);
                    float ix2 = fminf(kx2[j], b.w);
                    float inter = fmaxf(iy2 - iy1, 0.f) * fmaxf(ix2 - ix1, 0.f);
                    p = inter > IOU_THR * (karea[j] + area - inter + 1e-8f);
                }
                if (__ballot_sync(0xffffffffu, p)) { sup = true; break; }
            }
            if (!sup) {
                if (lane == 0) {
                    ky1[nk] = b.x; kx1[nk] = b.y; ky2[nk] = b.z; kx2[nk] = b.w; karea[nk] = area;
                }
                __syncwarp();
                nk++;
            }
        }
        if (lane == 0) s_nk = nk;
    }
    __syncthreads();

    int nk = s_nk;
    for (int s = tid; s < POST_NMS; s += blockDim.x) {
        float4 o = (s < nk) ? make_float4(ky1[s], kx1[s], ky2[s], kx2[s])
                            : make_float4(0.f, 0.f, 0.f, 0.f);
        *(float4*)&out_props[(size_t)s*4] = o;
    }
}

// ---------------- launch ----------------
extern "C" void kernel_launch(void* const* d_in, const int* in_sizes, int n_in,
                              void* d_out, int out_size)
{
    const float* feat = (const float*)d_in[1];
    const float* anch = (const float*)d_in[2];
    const float* W1   = (const float*)d_in[3];
    const float* b1   = (const float*)d_in[4];
    const float* Wc   = (const float*)d_in[5];
    const float* bc   = (const float*)d_in[6];
    const float* Wr   = (const float*)d_in[7];
    const float* br   = (const float*)d_in[8];
    float* out = (float*)d_out;

    cudaFuncSetAttribute(heads_kernel, cudaFuncAttributeMaxDynamicSharedMemorySize, 512*45*4);
    cudaFuncSetAttribute(sort_kernel,  cudaFuncAttributeMaxDynamicSharedMemorySize, CAND_CAP*8);
    cudaFuncSetAttribute(nms_kernel,   cudaFuncAttributeMaxDynamicSharedMemorySize, 96000 + 5*POST_NMS*4);

    zero_kernel<<<64, 1024>>>();
    conv_kernel<<<dim3(4, 125), 256>>>(feat, W1, b1);
    heads_kernel<<<NPIX/64, 256, 512*45*4>>>(Wc, bc, Wr, br, anch,
                                             out, out + NROW);
    thresh_kernel<<<1, 1024>>>();
    compact_kernel<<<(NROW + 255)/256, 256>>>();
    sort_kernel<<<1, 1024, CAND_CAP*8>>>();
    nms_kernel<<<1, 256, 96000 + 5*POST_NMS*4>>>(out + NROW + NROW*4);
}

// round 6
// speedup vs baseline: 1.0426x; 1.0426x over previous
#include <cuda_runtime.h>
#include <cuda_bf16.h>
#include <cstdint>
#include <math.h>

// ---------------- problem constants ----------------
#define HF 100
#define WF 160
#define NPIX (HF*WF)          // 16000
#define CIN 512
#define COC 512
#define NA 9
#define NROW (NPIX*NA)        // 144000
#define PRE_NMS 6000
#define POST_NMS 300
#define IMG_H 1600.0f
#define IMG_W 2560.0f
#define IOU_THR 0.7f
#define CAND_CAP 16384
#define KTOT 4608             // 9 taps * 512 channels
#define NSTG 144              // K stages of 32

// smem layout: 6 tiles per stage (Xh,Xm,Xl,Wh,Wm,Wl), each 128 rows x 32 bf16,
// rows padded to 40 bf16 (80 B) for conflict-free ldmatrix.
#define TILE_B 10240          // 128 * 80
#define STAGE_B (6*TILE_B)    // 61440
#define SMEM_TOT (3*STAGE_B)  // 184320

// ---------------- scratch (device globals; no cudaMalloc allowed) ----------------
__device__ __nv_bfloat16       g_Xh[NPIX*CIN], g_Xm[NPIX*CIN], g_Xl[NPIX*CIN];
__device__ __nv_bfloat16       g_Wh[COC*KTOT], g_Wm[COC*KTOT], g_Wl[COC*KTOT];
__device__ float               g_Y[NPIX*COC];       // conv output (relu'd)
__device__ float4              g_props[NROW];       // clipped proposals y1,x1,y2,x2
__device__ unsigned long long  g_keys[NROW];
__device__ unsigned int        g_hist[65536];
__device__ unsigned int        g_T;
__device__ unsigned long long  g_cand[CAND_CAP];
__device__ int                 g_cnt;
__device__ int                 g_rows[PRE_NMS];

// ---------------- small helpers ----------------
__device__ __forceinline__ uint32_t s2u(const void* p) {
    return (uint32_t)__cvta_generic_to_shared((void*)p);
}
__device__ __forceinline__ void cpa16(uint32_t dst, const void* src, int sz) {
    asm volatile("cp.async.cg.shared.global [%0], [%1], 16, %2;"
                 :: "r"(dst), "l"(src), "r"(sz) : "memory");
}

#define LDSM4(r0,r1,r2,r3,addr) \
    asm volatile("ldmatrix.sync.aligned.m8n8.x4.shared.b16 {%0,%1,%2,%3}, [%4];" \
        : "=r"(r0), "=r"(r1), "=r"(r2), "=r"(r3) : "r"(addr))
#define LDSM2(r0,r1,addr) \
    asm volatile("ldmatrix.sync.aligned.m8n8.x2.shared.b16 {%0,%1}, [%2];" \
        : "=r"(r0), "=r"(r1) : "r"(addr))

#define MMAB(acc, a, b) \
    asm volatile("mma.sync.aligned.m16n8k16.row.col.f32.bf16.bf16.f32 " \
        "{%0,%1,%2,%3}, {%4,%5,%6,%7}, {%8,%9}, {%0,%1,%2,%3};" \
        : "+f"((acc)[0]), "+f"((acc)[1]), "+f"((acc)[2]), "+f"((acc)[3]) \
        : "r"((a)[0]), "r"((a)[1]), "r"((a)[2]), "r"((a)[3]), \
          "r"((b)[0]), "r"((b)[1]))

// ---------------- zero counters ----------------
__global__ void zero_kernel() {
    int i = blockIdx.x * blockDim.x + threadIdx.x;
    if (i < 65536) g_hist[i] = 0u;
    if (i == 0) g_cnt = 0;
}

// ---------------- prep: split X into 3x bf16 (exact 24-bit cover) ----------------
__global__ __launch_bounds__(256) void split_x(const float* __restrict__ X) {
    int i = blockIdx.x * blockDim.x + threadIdx.x;
    if (i < NPIX * CIN) {
        float x = X[i];
        __nv_bfloat16 h = __float2bfloat16_rn(x);
        float r = x - __bfloat162float(h);
        __nv_bfloat16 m = __float2bfloat16_rn(r);
        float r2 = r - __bfloat162float(m);
        __nv_bfloat16 l = __float2bfloat16_rn(r2);
        g_Xh[i] = h; g_Xm[i] = m; g_Xl[i] = l;
    }
}

// ---------------- prep: transpose W [k][n] -> [n][k] + 3x bf16 split ----------------
__global__ void split_w(const float* __restrict__ W1) {
    __shared__ float ts[32][33];
    int kb = blockIdx.x * 32, nb = blockIdx.y * 32;
    int tx = threadIdx.x, ty = threadIdx.y;  // 32 x 8
    for (int r = ty; r < 32; r += 8)
        ts[r][tx] = W1[(size_t)(kb + r) * COC + nb + tx];
    __syncthreads();
    for (int r = ty; r < 32; r += 8) {
        float x = ts[tx][r];
        __nv_bfloat16 h = __float2bfloat16_rn(x);
        float rr = x - __bfloat162float(h);
        __nv_bfloat16 m = __float2bfloat16_rn(rr);
        float r2 = rr - __bfloat162float(m);
        __nv_bfloat16 l = __float2bfloat16_rn(r2);
        size_t o = (size_t)(nb + r) * KTOT + kb + tx;
        g_Wh[o] = h; g_Wm[o] = m; g_Wl[o] = l;
    }
}

// ---------------- conv 3x3 via bf16x8 mma.sync (fp32-faithful implicit GEMM) ----------------
// CTA: 128 pixels x 128 oc, BK=32. 8 warps: wm = wid&1 (64-row half),
// wn = wid>>1 (32-col quarter). 3-stage cp.async pipeline.
// Dual accumulator groups: acc0 = hh pass only; acc1 = 7 small passes.
__global__ __launch_bounds__(256, 1) void conv_mma(const float* __restrict__ b1) {
    extern __shared__ char smc[];
    uint32_t smem_u = s2u(smc);
    int tid = threadIdx.x;
    int lane = tid & 31, wid = tid >> 5;
    int wm = wid & 1, wn = wid >> 1;
    int lr = lane >> 2, lc = lane & 3;
    int bm = blockIdx.y;
    int n0 = blockIdx.x * 128;

    // loader mapping: thread handles rows (tid>>2) and (tid>>2)+64, 16B chunk (tid&3)
    int row0 = tid >> 2, c4 = tid & 3;
    int pix0 = bm * 128 + row0;
    int py0 = pix0 / WF, px0 = pix0 % WF;
    int pix1 = pix0 + 64;
    int py1 = pix1 / WF, px1 = pix1 % WF;
    uint32_t dstoff = (uint32_t)(row0 * 80 + c4 * 16);

    const __nv_bfloat16* gx[3] = {g_Xh, g_Xm, g_Xl};
    const __nv_bfloat16* gw[3] = {g_Wh, g_Wm, g_Wl};

    // ldmatrix per-lane offsets (bytes within tile)
    uint32_t aoff[4], boff[4];
    #pragma unroll
    for (int mf = 0; mf < 4; mf++)
        aoff[mf] = (uint32_t)((wm*64 + mf*16 + (lane & 15)) * 80 + ((lane >> 4) & 1) * 16);
    #pragma unroll
    for (int nf = 0; nf < 4; nf++)
        boff[nf] = (uint32_t)((wn*32 + nf*8 + (lane & 7)) * 80 + ((lane >> 3) & 1) * 16);

    float acc0[4][4][4], acc1[4][4][4];
    #pragma unroll
    for (int a = 0; a < 4; a++)
        #pragma unroll
        for (int b = 0; b < 4; b++)
            #pragma unroll
            for (int c = 0; c < 4; c++) { acc0[a][b][c] = 0.f; acc1[a][b][c] = 0.f; }

    auto load_stage = [&](int s) {
        uint32_t base = smem_u + (uint32_t)(s % 3) * STAGE_B;
        int tap = s >> 4;
        int cb  = (s & 15) << 5;          // channel base within tap
        int k0  = s << 5;                 // global K base (for W)
        int ky = tap / 3 - 1, kx = tap % 3 - 1;
        int hg0 = py0 + ky, wg0 = px0 + kx;
        int hg1 = py1 + ky, wg1 = px1 + kx;
        bool ok0 = ((unsigned)hg0 < HF) && ((unsigned)wg0 < WF);
        bool ok1 = ((unsigned)hg1 < HF) && ((unsigned)wg1 < WF);
        size_t xo0 = ok0 ? ((size_t)(hg0 * WF + wg0) * CIN + cb + c4 * 8) : 0;
        size_t xo1 = ok1 ? ((size_t)(hg1 * WF + wg1) * CIN + cb + c4 * 8) : 0;
        int sz0 = ok0 ? 16 : 0, sz1 = ok1 ? 16 : 0;
        #pragma unroll
        for (int lev = 0; lev < 3; lev++) {
            uint32_t d = base + lev * TILE_B + dstoff;
            cpa16(d,           gx[lev] + xo0, sz0);
            cpa16(d + 64*80,   gx[lev] + xo1, sz1);
        }
        size_t wo0 = (size_t)(n0 + row0) * KTOT + k0 + c4 * 8;
        size_t wo1 = wo0 + (size_t)64 * KTOT;
        #pragma unroll
        for (int lev = 0; lev < 3; lev++) {
            uint32_t d = base + (3 + lev) * TILE_B + dstoff;
            cpa16(d,           gw[lev] + wo0, 16);
            cpa16(d + 64*80,   gw[lev] + wo1, 16);
        }
    };

    load_stage(0);
    asm volatile("cp.async.commit_group;" ::: "memory");
    load_stage(1);
    asm volatile("cp.async.commit_group;" ::: "memory");

    for (int s = 0; s < NSTG; s++) {
        asm volatile("cp.async.wait_group 1;" ::: "memory");
        __syncthreads();
        if (s + 2 < NSTG) load_stage(s + 2);
        asm volatile("cp.async.commit_group;" ::: "memory");

        uint32_t st = smem_u + (uint32_t)(s % 3) * STAGE_B;

        #pragma unroll
        for (int ks = 0; ks < 2; ks++) {
            uint32_t kadd = (uint32_t)(ks * 32);     // 16 bf16 = 32 B
            // B fragments: 3 levels x 4 nf x 2 regs
            uint32_t bf[3][4][2];
            #pragma unroll
            for (int lev = 0; lev < 3; lev++)
                #pragma unroll
                for (int nf = 0; nf < 4; nf++)
                    LDSM2(bf[lev][nf][0], bf[lev][nf][1],
                          st + (3 + lev) * TILE_B + boff[nf] + kadd);

            // ---- A level h: hh -> acc0; hm, hl -> acc1 ----
            {
                uint32_t af[4][4];
                #pragma unroll
                for (int mf = 0; mf < 4; mf++)
                    LDSM4(af[mf][0], af[mf][1], af[mf][2], af[mf][3],
                          st + 0 * TILE_B + aoff[mf] + kadd);
                #pragma unroll
                for (int mf = 0; mf < 4; mf++)
                    #pragma unroll
                    for (int nf = 0; nf < 4; nf++)
                        MMAB(acc0[mf][nf], af[mf], bf[0][nf]);
                #pragma unroll
                for (int mf = 0; mf < 4; mf++)
                    #pragma unroll
                    for (int nf = 0; nf < 4; nf++)
                        MMAB(acc1[mf][nf], af[mf], bf[1][nf]);
                #pragma unroll
                for (int mf = 0; mf < 4; mf++)
                    #pragma unroll
                    for (int nf = 0; nf < 4; nf++)
                        MMAB(acc1[mf][nf], af[mf], bf[2][nf]);
            }
            // ---- A level m: mh, mm, ml -> acc1 ----
            {
                uint32_t af[4][4];
                #pragma unroll
                for (int mf = 0; mf < 4; mf++)
                    LDSM4(af[mf][0], af[mf][1], af[mf][2], af[mf][3],
                          st + 1 * TILE_B + aoff[mf] + kadd);
                #pragma unroll
                for (int lev = 0; lev < 3; lev++)
                    #pragma unroll
                    for (int mf = 0; mf < 4; mf++)
                        #pragma unroll
                        for (int nf = 0; nf < 4; nf++)
                            MMAB(acc1[mf][nf], af[mf], bf[lev][nf]);
            }
            // ---- A level l: lh, lm -> acc1 (ll omitted, ~2^-32) ----
            {
                uint32_t af[4][4];
                #pragma unroll
                for (int mf = 0; mf < 4; mf++)
                    LDSM4(af[mf][0], af[mf][1], af[mf][2], af[mf][3],
                          st + 2 * TILE_B + aoff[mf] + kadd);
                #pragma unroll
                for (int lev = 0; lev < 2; lev++)
                    #pragma unroll
                    for (int mf = 0; mf < 4; mf++)
                        #pragma unroll
                        for (int nf = 0; nf < 4; nf++)
                            MMAB(acc1[mf][nf], af[mf], bf[lev][nf]);
            }
        }
        __syncthreads();
    }

    // epilogue: combine accumulator groups, +bias, relu, float2 stores
    #pragma unroll
    for (int mf = 0; mf < 4; mf++) {
        int pix = bm*128 + wm*64 + mf*16 + lr;
        #pragma unroll
        for (int nf = 0; nf < 4; nf++) {
            int oc = n0 + wn*32 + nf*8 + 2*lc;
            float2 bb = *(const float2*)&b1[oc];
            float2 v0, v1;
            v0.x = fmaxf(acc0[mf][nf][0] + acc1[mf][nf][0] + bb.x, 0.f);
            v0.y = fmaxf(acc0[mf][nf][1] + acc1[mf][nf][1] + bb.y, 0.f);
            v1.x = fmaxf(acc0[mf][nf][2] + acc1[mf][nf][2] + bb.x, 0.f);
            v1.y = fmaxf(acc0[mf][nf][3] + acc1[mf][nf][3] + bb.y, 0.f);
            *(float2*)&g_Y[(size_t)pix * COC + oc]       = v0;
            *(float2*)&g_Y[(size_t)(pix + 8) * COC + oc] = v1;
        }
    }
}

// ---------------- heads: 1x1 convs + softmax + decode + keys + hist ----------------
__global__ __launch_bounds__(256) void heads_kernel(
    const float* __restrict__ Wc, const float* __restrict__ bc,
    const float* __restrict__ Wr, const float* __restrict__ br,
    const float* __restrict__ anch,
    float* __restrict__ out_scores, float* __restrict__ out_deltas)
{
    extern __shared__ float sW[];   // [512][45]: [0..8]=Wc, [9..44]=Wr
    int tid = threadIdx.x;
    for (int i = tid; i < 512*9;  i += blockDim.x) { int c = i/9;  int o = i%9;  sW[c*45 + o]     = Wc[i]; }
    for (int i = tid; i < 512*36; i += blockDim.x) { int c = i/36; int o = i%36; sW[c*45 + 9 + o] = Wr[i]; }
    __syncthreads();

    int warp = tid >> 5, lane = tid & 31;

    for (int it = 0; it < 8; it++) {
        int pix = blockIdx.x*64 + warp*8 + it;
        const float* yrow = g_Y + (size_t)pix*COC;

        float acc[45];
        #pragma unroll
        for (int o = 0; o < 45; o++) acc[o] = 0.f;

        #pragma unroll
        for (int i = 0; i < 16; i++) {
            int c = lane + 32*i;
            float yv = yrow[c];
            const float* w = &sW[c*45];
            #pragma unroll
            for (int o = 0; o < 45; o++) acc[o] += yv * w[o];
        }
        #pragma unroll
        for (int o = 0; o < 45; o++) {
            float v = acc[o];
            v += __shfl_xor_sync(0xffffffffu, v, 16);
            v += __shfl_xor_sync(0xffffffffu, v, 8);
            v += __shfl_xor_sync(0xffffffffu, v, 4);
            v += __shfl_xor_sync(0xffffffffu, v, 2);
            v += __shfl_xor_sync(0xffffffffu, v, 1);
            acc[o] = v;
        }

        if (lane < 9) {
            int a = lane;
            int r = pix*9 + a;
            float lg[9];
            #pragma unroll
            for (int o = 0; o < 9; o++) lg[o] = acc[o] + bc[o];
            float mx = lg[0];
            #pragma unroll
            for (int o = 1; o < 9; o++) mx = fmaxf(mx, lg[o]);
            float den = 0.f;
            #pragma unroll
            for (int o = 0; o < 9; o++) den += expf(lg[o] - mx);
            float score = expf(lg[a] - mx) / den;
            out_scores[r] = score;

            float d0 = acc[9 + 4*a + 0] + br[4*a + 0];
            float d1 = acc[9 + 4*a + 1] + br[4*a + 1];
            float d2 = acc[9 + 4*a + 2] + br[4*a + 2];
            float d3 = acc[9 + 4*a + 3] + br[4*a + 3];
            out_deltas[(size_t)r*4 + 0] = d0;
            out_deltas[(size_t)r*4 + 1] = d1;
            out_deltas[(size_t)r*4 + 2] = d2;
            out_deltas[(size_t)r*4 + 3] = d3;

            float4 an = ((const float4*)anch)[r];   // cy,cx,h,w
            float cy = an.x + d0*an.z;
            float cx = an.y + d1*an.w;
            float sy = an.z * expf(d2);
            float sx = an.w * expf(d3);
            float y1 = fmaxf(cy - 0.5f*sy, 0.f);
            float x1 = fmaxf(cx - 0.5f*sx, 0.f);
            float y2 = fminf(cy + 0.5f*sy, IMG_H);
            float x2 = fminf(cx + 0.5f*sx, IMG_W);
            g_props[r] = make_float4(y1, x1, y2, x2);

            unsigned sb = __float_as_uint(score);
            g_keys[r] = ((unsigned long long)sb << 32) | (0xFFFFFFFFu - (unsigned)r);
            atomicAdd(&g_hist[sb >> 16], 1u);
        }
    }
}

// ---------------- threshold bin so that count(bin >= T) >= PRE_NMS ----------------
__global__ void thresh_kernel() {
    __shared__ unsigned int csum[1024];
    int t = threadIdx.x;
    int hi = 65535 - t*64;
    unsigned s = 0;
    for (int b = 0; b < 64; b++) s += g_hist[hi - b];
    csum[t] = s;
    __syncthreads();
    if (t == 0) {
        unsigned cum = 0; unsigned T = 0; bool found = false;
        for (int i = 0; i < 1024 && !found; i++) {
            if (cum + csum[i] >= PRE_NMS) {
                int hb = 65535 - i*64;
                for (int b = 0; b < 64; b++) {
                    cum += g_hist[hb - b];
                    if (cum >= PRE_NMS) { T = (unsigned)(hb - b); found = true; break; }
                }
            } else cum += csum[i];
        }
        g_T = T;
    }
}

// ---------------- compact candidates with bin >= T ----------------
__global__ void compact_kernel() {
    int r = blockIdx.x*blockDim.x + threadIdx.x;
    if (r >= NROW) return;
    unsigned long long k = g_keys[r];
    if ((unsigned)(k >> 48) >= g_T) {
        int p = atomicAdd(&g_cnt, 1);
        if (p < CAND_CAP) g_cand[p] = k;
    }
}

// ---------------- one-block bitonic sort (descending) ----------------
__global__ __launch_bounds__(1024) void sort_kernel() {
    extern __shared__ unsigned long long sk[];   // 16384 * 8 = 128 KB
    int n = g_cnt; if (n > CAND_CAP) n = CAND_CAP;
    for (int i = threadIdx.x; i < CAND_CAP; i += 1024)
        sk[i] = (i < n) ? g_cand[i] : 0ULL;
    __syncthreads();

    for (int k = 2; k <= CAND_CAP; k <<= 1) {
        for (int j = k >> 1; j > 0; j >>= 1) {
            for (int i = threadIdx.x; i < CAND_CAP; i += 1024) {
                int ixj = i ^ j;
                if (ixj > i) {
                    unsigned long long a = sk[i], b = sk[ixj];
                    bool descBlock = ((i & k) == 0);
                    bool doSwap = descBlock ? (a < b) : (a > b);
                    if (doSwap) { sk[i] = b; sk[ixj] = a; }
                }
            }
            __syncthreads();
        }
    }
    for (int i = threadIdx.x; i < PRE_NMS; i += 1024)
        g_rows[i] = (int)(0xFFFFFFFFu - (unsigned)(sk[i] & 0xFFFFFFFFULL));
}

// ---------------- greedy NMS on sorted list ----------------
__global__ __launch_bounds__(256) void nms_kernel(float* __restrict__ out_props) {
    extern __shared__ unsigned char smem[];
    float4* box  = (float4*)smem;                       // 6000 * 16 = 96000 B
    float*  ky1  = (float*)(smem + 96000);              // 300
    float*  kx1  = ky1 + POST_NMS;
    float*  ky2  = kx1 + POST_NMS;
    float*  kx2  = ky2 + POST_NMS;
    float*  karea= kx2 + POST_NMS;
    __shared__ int s_nk;

    int tid = threadIdx.x;
    for (int i = tid; i < PRE_NMS; i += blockDim.x)
        box[i] = g_props[g_rows[i]];
    __syncthreads();

    if (tid < 32) {
        int lane = tid;
        int nk = 0;
        for (int i = 0; i < PRE_NMS && nk < POST_NMS; i++) {
            float4 b = box[i];
            float h = b.z - b.x, w = b.w - b.y;
            if (h < 16.f || w < 16.f) continue;
            float area = h * w;
            bool sup = false;
            for (int j0 = 0; j0 < nk; j0 += 32) {
                int j = j0 + lane;
                bool p = false;
                if (j < nk) {
                    float iy1 = fmaxf(ky1[j], b.x);
                    float ix1 = fmaxf(kx1[j], b.y);
                    float iy2 = fminf(ky2[j], b.z);
                    float ix2 = fminf(kx2[j], b.w);
                    float inter = fmaxf(iy2 - iy1, 0.f) * fmaxf(ix2 - ix1, 0.f);
                    p = inter > IOU_THR * (karea[j] + area - inter + 1e-8f);
                }
                if (__ballot_sync(0xffffffffu, p)) { sup = true; break; }
            }
            if (!sup) {
                if (lane == 0) {
                    ky1[nk] = b.x; kx1[nk] = b.y; ky2[nk] = b.z; kx2[nk] = b.w; karea[nk] = area;
                }
                __syncwarp();
                nk++;
            }
        }
        if (lane == 0) s_nk = nk;
    }
    __syncthreads();

    int nk = s_nk;
    for (int s = tid; s < POST_NMS; s += blockDim.x) {
        float4 o = (s < nk) ? make_float4(ky1[s], kx1[s], ky2[s], kx2[s])
                            : make_float4(0.f, 0.f, 0.f, 0.f);
        *(float4*)&out_props[(size_t)s*4] = o;
    }
}

// ---------------- launch ----------------
extern "C" void kernel_launch(void* const* d_in, const int* in_sizes, int n_in,
                              void* d_out, int out_size)
{
    const float* feat = (const float*)d_in[1];
    const float* anch = (const float*)d_in[2];
    const float* W1   = (const float*)d_in[3];
    const float* b1   = (const float*)d_in[4];
    const float* Wc   = (const float*)d_in[5];
    const float* bc   = (const float*)d_in[6];
    const float* Wr   = (const float*)d_in[7];
    const float* br   = (const float*)d_in[8];
    float* out = (float*)d_out;

    cudaFuncSetAttribute(conv_mma,     cudaFuncAttributeMaxDynamicSharedMemorySize, SMEM_TOT);
    cudaFuncSetAttribute(heads_kernel, cudaFuncAttributeMaxDynamicSharedMemorySize, 512*45*4);
    cudaFuncSetAttribute(sort_kernel,  cudaFuncAttributeMaxDynamicSharedMemorySize, CAND_CAP*8);
    cudaFuncSetAttribute(nms_kernel,   cudaFuncAttributeMaxDynamicSharedMemorySize, 96000 + 5*POST_NMS*4);

    zero_kernel<<<64, 1024>>>();
    split_x<<<(NPIX*CIN + 255)/256, 256>>>(feat);
    split_w<<<dim3(KTOT/32, COC/32), dim3(32, 8)>>>(W1);
    conv_mma<<<dim3(4, 125), 256, SMEM_TOT>>>(b1);
    heads_kernel<<<NPIX/64, 256, 512*45*4>>>(Wc, bc, Wr, br, anch,
                                             out, out + NROW);
    thresh_kernel<<<1, 1024>>>();
    compact_kernel<<<(NROW + 255)/256, 256>>>();
    sort_kernel<<<1, 1024, CAND_CAP*8>>>();
    nms_kernel<<<1, 256, 96000 + 5*POST_NMS*4>>>(out + NROW + NROW*4);
}

// round 12
// speedup vs baseline: 1.0750x; 1.0310x over previous
#include <cuda_runtime.h>
#include <cuda_bf16.h>
#include <cstdint>
#include <math.h>

// ---------------- problem constants ----------------
#define HF 100
#define WF 160
#define NPIX (HF*WF)          // 16000
#define CIN 512
#define COC 512
#define NA 9
#define NROW (NPIX*NA)        // 144000
#define PRE_NMS 6000
#define POST_NMS 300
#define IMG_H 1600.0f
#define IMG_W 2560.0f
#define IOU_THR 0.7f
#define CAND_CAP 16384
#define KTOT 4608             // 9 taps * 512 channels
#define NSTG 144              // K stages of 32

// conv tiling: 128(pixels) x 64(oc) tiles, 1000 tiles, persistent 148 CTAs
#define NTILE 1000
#define XT_B 10240            // X tile: 128 rows x 80 B
#define WT_B 5120             // W tile: 64 rows x 80 B
#define STAGE_B (3*XT_B + 3*WT_B)   // 46080
#define NBUF 4
#define SMEM_TOT (NBUF*STAGE_B)     // 184320

#define NMSB 94               // ceil(6000/64) mask words per row

// ---------------- scratch (device globals; no cudaMalloc allowed) ----------------
__device__ __nv_bfloat16       g_Xh[NPIX*CIN], g_Xm[NPIX*CIN], g_Xl[NPIX*CIN];
__device__ __nv_bfloat16       g_Wh[COC*KTOT], g_Wm[COC*KTOT], g_Wl[COC*KTOT];
__device__ float               g_Y[NPIX*COC];       // conv output (relu'd)
__device__ float4              g_props[NROW];       // clipped proposals y1,x1,y2,x2
__device__ unsigned long long  g_keys[NROW];
__device__ unsigned int        g_hist[65536];
__device__ unsigned int        g_T;
__device__ unsigned long long  g_cand[CAND_CAP];
__device__ int                 g_cnt;
__device__ int                 g_rows[PRE_NMS];
__device__ float4              g_box[PRE_NMS];      // sorted candidate boxes
__device__ unsigned long long  g_mask[PRE_NMS*NMSB];// suppression bitmask

// ---------------- small helpers ----------------
__device__ __forceinline__ uint32_t s2u(const void* p) {
    return (uint32_t)__cvta_generic_to_shared((void*)p);
}
__device__ __forceinline__ void cpa16(uint32_t dst, const void* src, int sz) {
    asm volatile("cp.async.cg.shared.global [%0], [%1], 16, %2;"
                 :: "r"(dst), "l"(src), "r"(sz) : "memory");
}

#define LDSM4(r0,r1,r2,r3,addr) \
    asm volatile("ldmatrix.sync.aligned.m8n8.x4.shared.b16 {%0,%1,%2,%3}, [%4];" \
        : "=r"(r0), "=r"(r1), "=r"(r2), "=r"(r3) : "r"(addr))
#define LDSM2(r0,r1,addr) \
    asm volatile("ldmatrix.sync.aligned.m8n8.x2.shared.b16 {%0,%1}, [%2];" \
        : "=r"(r0), "=r"(r1) : "r"(addr))

#define MMAB(acc, a, b) \
    asm volatile("mma.sync.aligned.m16n8k16.row.col.f32.bf16.bf16.f32 " \
        "{%0,%1,%2,%3}, {%4,%5,%6,%7}, {%8,%9}, {%0,%1,%2,%3};" \
        : "+f"((acc)[0]), "+f"((acc)[1]), "+f"((acc)[2]), "+f"((acc)[3]) \
        : "r"((a)[0]), "r"((a)[1]), "r"((a)[2]), "r"((a)[3]), \
          "r"((b)[0]), "r"((b)[1]))

// ---------------- zero counters ----------------
__global__ void zero_kernel() {
    int i = blockIdx.x * blockDim.x + threadIdx.x;
    if (i < 65536) g_hist[i] = 0u;
    if (i == 0) g_cnt = 0;
}

// ---------------- prep: split X into 3x bf16 (exact 24-bit cover) ----------------
__global__ __launch_bounds__(256) void split_x(const float* __restrict__ X) {
    int i = blockIdx.x * blockDim.x + threadIdx.x;
    if (i < NPIX * CIN) {
        float x = X[i];
        __nv_bfloat16 h = __float2bfloat16_rn(x);
        float r = x - __bfloat162float(h);
        __nv_bfloat16 m = __float2bfloat16_rn(r);
        float r2 = r - __bfloat162float(m);
        __nv_bfloat16 l = __float2bfloat16_rn(r2);
        g_Xh[i] = h; g_Xm[i] = m; g_Xl[i] = l;
    }
}

// ---------------- prep: transpose W [k][n] -> [n][k] + 3x bf16 split ----------------
__global__ void split_w(const float* __restrict__ W1) {
    __shared__ float ts[32][33];
    int kb = blockIdx.x * 32, nb = blockIdx.y * 32;
    int tx = threadIdx.x, ty = threadIdx.y;  // 32 x 8
    for (int r = ty; r < 32; r += 8)
        ts[r][tx] = W1[(size_t)(kb + r) * COC + nb + tx];
    __syncthreads();
    for (int r = ty; r < 32; r += 8) {
        float x = ts[tx][r];
        __nv_bfloat16 h = __float2bfloat16_rn(x);
        float rr = x - __bfloat162float(h);
        __nv_bfloat16 m = __float2bfloat16_rn(rr);
        float r2 = rr - __bfloat162float(m);
        __nv_bfloat16 l = __float2bfloat16_rn(r2);
        size_t o = (size_t)(nb + r) * KTOT + kb + tx;
        g_Wh[o] = h; g_Wm[o] = m; g_Wl[o] = l;
    }
}

// ---------------- conv 3x3: persistent bf16x8 mma.sync implicit GEMM ----------------
// Tile 128(pix) x 64(oc), BK=32, 4-stage cp.async pipeline, 1 sync/stage.
// 8 warps: wm = wid&3 (32-row quarter), wn = wid>>2 (32-col half).
__global__ __launch_bounds__(256, 1) void conv_mma(const float* __restrict__ b1) {
    extern __shared__ char smc[];
    uint32_t smem_u = s2u(smc);
    int tid = threadIdx.x;
    int lane = tid & 31, wid = tid >> 5;
    int wm = wid & 3, wn = wid >> 2;
    int lr = lane >> 2, lc = lane & 3;

    int row0 = tid >> 2, c4 = tid & 3;      // loader: row slot + 16B chunk
    uint32_t dstoff = (uint32_t)(row0 * 80 + c4 * 16);

    const __nv_bfloat16* gx[3] = {g_Xh, g_Xm, g_Xl};
    const __nv_bfloat16* gw[3] = {g_Wh, g_Wm, g_Wl};

    uint32_t aoff[2], boff[4];
    #pragma unroll
    for (int mf = 0; mf < 2; mf++)
        aoff[mf] = (uint32_t)((wm*32 + mf*16 + (lane & 15)) * 80 + ((lane >> 4) & 1) * 16);
    #pragma unroll
    for (int nf = 0; nf < 4; nf++)
        boff[nf] = (uint32_t)((wn*32 + nf*8 + (lane & 7)) * 80 + ((lane >> 3) & 1) * 16);

    for (int tile = blockIdx.x; tile < NTILE; tile += gridDim.x) {
        int bn = tile & 7, bm = tile >> 3;
        int n0 = bn * 64;
        int pix0 = bm * 128 + row0;
        int py0 = pix0 / WF, px0 = pix0 % WF;
        int pix1 = pix0 + 64;
        int py1 = pix1 / WF, px1 = pix1 % WF;

        float acc0[2][4][4], acc1[2][4][4];
        #pragma unroll
        for (int a = 0; a < 2; a++)
            #pragma unroll
            for (int b = 0; b < 4; b++)
                #pragma unroll
                for (int c = 0; c < 4; c++) { acc0[a][b][c] = 0.f; acc1[a][b][c] = 0.f; }

        auto load_stage = [&](int s) {
            uint32_t base = smem_u + (uint32_t)(s % NBUF) * STAGE_B;
            int tap = s >> 4;
            int cb  = (s & 15) << 5;
            int k0  = s << 5;
            int ky = tap / 3 - 1, kx = tap % 3 - 1;
            int hg0 = py0 + ky, wg0 = px0 + kx;
            int hg1 = py1 + ky, wg1 = px1 + kx;
            bool ok0 = ((unsigned)hg0 < HF) && ((unsigned)wg0 < WF);
            bool ok1 = ((unsigned)hg1 < HF) && ((unsigned)wg1 < WF);
            size_t xo0 = ok0 ? ((size_t)(hg0 * WF + wg0) * CIN + cb + c4 * 8) : 0;
            size_t xo1 = ok1 ? ((size_t)(hg1 * WF + wg1) * CIN + cb + c4 * 8) : 0;
            int sz0 = ok0 ? 16 : 0, sz1 = ok1 ? 16 : 0;
            #pragma unroll
            for (int lev = 0; lev < 3; lev++) {
                uint32_t d = base + lev * XT_B + dstoff;
                cpa16(d,           gx[lev] + xo0, sz0);
                cpa16(d + 64*80,   gx[lev] + xo1, sz1);
            }
            size_t wo = (size_t)(n0 + row0) * KTOT + k0 + c4 * 8;
            #pragma unroll
            for (int lev = 0; lev < 3; lev++)
                cpa16(base + 3*XT_B + lev * WT_B + dstoff, gw[lev] + wo, 16);
        };

        load_stage(0);
        asm volatile("cp.async.commit_group;" ::: "memory");
        load_stage(1);
        asm volatile("cp.async.commit_group;" ::: "memory");
        load_stage(2);
        asm volatile("cp.async.commit_group;" ::: "memory");

        for (int s = 0; s < NSTG; s++) {
            asm volatile("cp.async.wait_group 2;" ::: "memory");
            __syncthreads();
            if (s + 3 < NSTG) load_stage(s + 3);
            asm volatile("cp.async.commit_group;" ::: "memory");

            uint32_t st = smem_u + (uint32_t)(s % NBUF) * STAGE_B;

            #pragma unroll
            for (int ks = 0; ks < 2; ks++) {
                uint32_t kadd = (uint32_t)(ks * 32);
                uint32_t bf[3][4][2];
                #pragma unroll
                for (int lev = 0; lev < 3; lev++)
                    #pragma unroll
                    for (int nf = 0; nf < 4; nf++)
                        LDSM2(bf[lev][nf][0], bf[lev][nf][1],
                              st + 3*XT_B + lev * WT_B + boff[nf] + kadd);

                // A level h: hh -> acc0; hm, hl -> acc1
                {
                    uint32_t af[2][4];
                    #pragma unroll
                    for (int mf = 0; mf < 2; mf++)
                        LDSM4(af[mf][0], af[mf][1], af[mf][2], af[mf][3],
                              st + 0 * XT_B + aoff[mf] + kadd);
                    #pragma unroll
                    for (int mf = 0; mf < 2; mf++)
                        #pragma unroll
                        for (int nf = 0; nf < 4; nf++)
                            MMAB(acc0[mf][nf], af[mf], bf[0][nf]);
                    #pragma unroll
                    for (int mf = 0; mf < 2; mf++)
                        #pragma unroll
                        for (int nf = 0; nf < 4; nf++)
                            MMAB(acc1[mf][nf], af[mf], bf[1][nf]);
                    #pragma unroll
                    for (int mf = 0; mf < 2; mf++)
                        #pragma unroll
                        for (int nf = 0; nf < 4; nf++)
                            MMAB(acc1[mf][nf], af[mf], bf[2][nf]);
                }
                // A level m: mh, mm, ml -> acc1
                {
                    uint32_t af[2][4];
                    #pragma unroll
                    for (int mf = 0; mf < 2; mf++)
                        LDSM4(af[mf][0], af[mf][1], af[mf][2], af[mf][3],
                              st + 1 * XT_B + aoff[mf] + kadd);
                    #pragma unroll
                    for (int lev = 0; lev < 3; lev++)
                        #pragma unroll
                        for (int mf = 0; mf < 2; mf++)
                            #pragma unroll
                            for (int nf = 0; nf < 4; nf++)
                                MMAB(acc1[mf][nf], af[mf], bf[lev][nf]);
                }
                // A level l: lh, lm -> acc1 (ll omitted, ~2^-34)
                {
                    uint32_t af[2][4];
                    #pragma unroll
                    for (int mf = 0; mf < 2; mf++)
                        LDSM4(af[mf][0], af[mf][1], af[mf][2], af[mf][3],
                              st + 2 * XT_B + aoff[mf] + kadd);
                    #pragma unroll
                    for (int lev = 0; lev < 2; lev++)
                        #pragma unroll
                        for (int mf = 0; mf < 2; mf++)
                            #pragma unroll
                            for (int nf = 0; nf < 4; nf++)
                                MMAB(acc1[mf][nf], af[mf], bf[lev][nf]);
                }
            }
        }

        // epilogue: combine groups, +bias, relu
        #pragma unroll
        for (int mf = 0; mf < 2; mf++) {
            int pix = bm*128 + wm*32 + mf*16 + lr;
            #pragma unroll
            for (int nf = 0; nf < 4; nf++) {
                int oc = n0 + wn*32 + nf*8 + 2*lc;
                float2 bb = *(const float2*)&b1[oc];
                float2 v0, v1;
                v0.x = fmaxf(acc0[mf][nf][0] + acc1[mf][nf][0] + bb.x, 0.f);
                v0.y = fmaxf(acc0[mf][nf][1] + acc1[mf][nf][1] + bb.y, 0.f);
                v1.x = fmaxf(acc0[mf][nf][2] + acc1[mf][nf][2] + bb.x, 0.f);
                v1.y = fmaxf(acc0[mf][nf][3] + acc1[mf][nf][3] + bb.y, 0.f);
                *(float2*)&g_Y[(size_t)pix * COC + oc]       = v0;
                *(float2*)&g_Y[(size_t)(pix + 8) * COC + oc] = v1;
            }
        }
        // next tile's preload overwrites buffers 0..2, all last read >=1 sync ago;
        // buffer 3 (stage 143) is only rewritten after next tile's s=0 sync.
    }
}

// ---------------- heads: 1x1 convs + softmax + decode + keys + hist ----------------
__global__ __launch_bounds__(256) void heads_kernel(
    const float* __restrict__ Wc, const float* __restrict__ bc,
    const float* __restrict__ Wr, const float* __restrict__ br,
    const float* __restrict__ anch,
    float* __restrict__ out_scores, float* __restrict__ out_deltas)
{
    extern __shared__ float sW[];   // [512][45]
    int tid = threadIdx.x;
    for (int i = tid; i < 512*9;  i += blockDim.x) { int c = i/9;  int o = i%9;  sW[c*45 + o]     = Wc[i]; }
    for (int i = tid; i < 512*36; i += blockDim.x) { int c = i/36; int o = i%36; sW[c*45 + 9 + o] = Wr[i]; }
    __syncthreads();

    int warp = tid >> 5, lane = tid & 31;

    for (int it = 0; it < 8; it++) {
        int pix = blockIdx.x*64 + warp*8 + it;
        const float* yrow = g_Y + (size_t)pix*COC;

        float acc[45];
        #pragma unroll
        for (int o = 0; o < 45; o++) acc[o] = 0.f;

        #pragma unroll
        for (int i = 0; i < 16; i++) {
            int c = lane + 32*i;
            float yv = yrow[c];
            const float* w = &sW[c*45];
            #pragma unroll
            for (int o = 0; o < 45; o++) acc[o] += yv * w[o];
        }
        #pragma unroll
        for (int o = 0; o < 45; o++) {
            float v = acc[o];
            v += __shfl_xor_sync(0xffffffffu, v, 16);
            v += __shfl_xor_sync(0xffffffffu, v, 8);
            v += __shfl_xor_sync(0xffffffffu, v, 4);
            v += __shfl_xor_sync(0xffffffffu, v, 2);
            v += __shfl_xor_sync(0xffffffffu, v, 1);
            acc[o] = v;
        }

        if (lane < 9) {
            int a = lane;
            int r = pix*9 + a;
            float lg[9];
            #pragma unroll
            for (int o = 0; o < 9; o++) lg[o] = acc[o] + bc[o];
            float mx = lg[0];
            #pragma unroll
            for (int o = 1; o < 9; o++) mx = fmaxf(mx, lg[o]);
            float den = 0.f;
            #pragma unroll
            for (int o = 0; o < 9; o++) den += expf(lg[o] - mx);
            float score = expf(lg[a] - mx) / den;
            out_scores[r] = score;

            float d0 = acc[9 + 4*a + 0] + br[4*a + 0];
            float d1 = acc[9 + 4*a + 1] + br[4*a + 1];
            float d2 = acc[9 + 4*a + 2] + br[4*a + 2];
            float d3 = acc[9 + 4*a + 3] + br[4*a + 3];
            out_deltas[(size_t)r*4 + 0] = d0;
            out_deltas[(size_t)r*4 + 1] = d1;
            out_deltas[(size_t)r*4 + 2] = d2;
            out_deltas[(size_t)r*4 + 3] = d3;

            float4 an = ((const float4*)anch)[r];   // cy,cx,h,w
            float cy = an.x + d0*an.z;
            float cx = an.y + d1*an.w;
            float sy = an.z * expf(d2);
            float sx = an.w * expf(d3);
            float y1 = fmaxf(cy - 0.5f*sy, 0.f);
            float x1 = fmaxf(cx - 0.5f*sx, 0.f);
            float y2 = fminf(cy + 0.5f*sy, IMG_H);
            float x2 = fminf(cx + 0.5f*sx, IMG_W);
            g_props[r] = make_float4(y1, x1, y2, x2);

            unsigned sb = __float_as_uint(score);
            g_keys[r] = ((unsigned long long)sb << 32) | (0xFFFFFFFFu - (unsigned)r);
            atomicAdd(&g_hist[sb >> 16], 1u);
        }
    }
}

// ---------------- threshold: vectorized hist sums + block scan ----------------
__global__ __launch_bounds__(1024) void thresh_kernel() {
    __shared__ unsigned wsum[32];
    int t = threadIdx.x;
    int hi = 65535 - t*64;          // chunk t covers bins [hi-63, hi], descending chunks
    const uint4* p = (const uint4*)(g_hist + (hi - 63));
    unsigned s = 0;
    #pragma unroll
    for (int q = 0; q < 16; q++) { uint4 v = p[q]; s += v.x + v.y + v.z + v.w; }

    // block inclusive scan of s over 1024 threads
    unsigned c = s;
    #pragma unroll
    for (int o = 1; o < 32; o <<= 1) {
        unsigned n = __shfl_up_sync(0xffffffffu, c, o);
        if ((t & 31) >= o) c += n;
    }
    if ((t & 31) == 31) wsum[t >> 5] = c;
    __syncthreads();
    if (t < 32) {
        unsigned wv = wsum[t];
        #pragma unroll
        for (int o = 1; o < 32; o <<= 1) {
            unsigned n = __shfl_up_sync(0xffffffffu, wv, o);
            if (t >= o) wv += n;
        }
        wsum[t] = wv;
    }
    __syncthreads();
    unsigned pre = (t >> 5) ? wsum[(t >> 5) - 1] : 0u;
    unsigned C = c + pre;           // inclusive
    unsigned E = C - s;             // exclusive
    if (E < PRE_NMS && C >= PRE_NMS) {
        unsigned cum = E;
        unsigned T = (unsigned)(hi - 63);
        for (int b = 0; b < 64; b++) {
            cum += g_hist[hi - b];
            if (cum >= PRE_NMS) { T = (unsigned)(hi - b); break; }
        }
        g_T = T;
    }
}

// ---------------- compact candidates with bin >= T ----------------
__global__ void compact_kernel() {
    int r = blockIdx.x*blockDim.x + threadIdx.x;
    if (r >= NROW) return;
    unsigned long long k = g_keys[r];
    if ((unsigned)(k >> 48) >= g_T) {
        int p = atomicAdd(&g_cnt, 1);
        if (p < CAND_CAP) g_cand[p] = k;
    }
}

// ---------------- one-block bitonic sort (descending) + gather ----------------
__global__ __launch_bounds__(1024) void sort_kernel() {
    extern __shared__ unsigned long long sk[];   // 16384 * 8 = 128 KB
    int n = g_cnt; if (n > CAND_CAP) n = CAND_CAP;
    for (int i = threadIdx.x; i < CAND_CAP; i += 1024)
        sk[i] = (i < n) ? g_cand[i] : 0ULL;
    __syncthreads();

    for (int k = 2; k <= CAND_CAP; k <<= 1) {
        for (int j = k >> 1; j > 0; j >>= 1) {
            for (int i = threadIdx.x; i < CAND_CAP; i += 1024) {
                int ixj = i ^ j;
                if (ixj > i) {
                    unsigned long long a = sk[i], b = sk[ixj];
                    bool descBlock = ((i & k) == 0);
                    bool doSwap = descBlock ? (a < b) : (a > b);
                    if (doSwap) { sk[i] = b; sk[ixj] = a; }
                }
            }
            __syncthreads();
        }
    }
    for (int i = threadIdx.x; i < PRE_NMS; i += 1024) {
        int r = (int)(0xFFFFFFFFu - (unsigned)(sk[i] & 0xFFFFFFFFULL));
        g_rows[i] = r;
        g_box[i] = g_props[r];
    }
}

// ---------------- NMS phase A: suppression bitmask (i suppresses j>i) ----------------
__global__ __launch_bounds__(64) void nms_mask_kernel() {
    int bi = blockIdx.y, bj = blockIdx.x;
    int t = threadIdx.x;
    int i = bi*64 + t;
    if (bj < bi) {
        if (i < PRE_NMS) g_mask[(size_t)i*NMSB + bj] = 0ull;
        return;
    }
    __shared__ float4 jb[64];
    int j0 = bj*64 + t;
    jb[t] = (j0 < PRE_NMS) ? g_box[j0] : make_float4(0.f,0.f,0.f,0.f);
    __syncthreads();
    if (i >= PRE_NMS) return;
    float4 a = g_box[i];
    float aarea = (a.z - a.x) * (a.w - a.y);
    unsigned long long bits = 0ull;
    #pragma unroll 4
    for (int jj = 0; jj < 64; jj++) {
        int j = bj*64 + jj;
        if (j <= i) continue;
        float4 c = jb[jj];
        float iy1 = fmaxf(a.x, c.x), ix1 = fmaxf(a.y, c.y);
        float iy2 = fminf(a.z, c.z), ix2 = fminf(a.w, c.w);
        float inter = fmaxf(iy2 - iy1, 0.f) * fmaxf(ix2 - ix1, 0.f);
        float carea = (c.z - c.x) * (c.w - c.y);
        if (inter > IOU_THR * (aarea + carea - inter + 1e-8f)) bits |= (1ull << jj);
    }
    g_mask[(size_t)i*NMSB + bj] = bits;
}

// ---------------- NMS phase B: single-warp sweep over bitmask ----------------
__global__ __launch_bounds__(1024) void nms_sweep(float* __restrict__ out_props) {
    extern __shared__ unsigned char smem[];
    float4* sbox = (float4*)smem;                 // 6000 * 16 = 96000 B
    int* skeep = (int*)(smem + 96000);            // 300 ints
    __shared__ int s_nk;

    int tid = threadIdx.x;
    for (int i = tid; i < PRE_NMS; i += blockDim.x)
        sbox[i] = g_box[i];
    __syncthreads();

    if (tid < 32) {
        int L = tid;
        unsigned long long s0 = 0ull, s1 = 0ull, s2 = 0ull;
        int kept = 0;
        for (int w = 0; w < NMSB && kept < POST_NMS; w++) {
            int slot = w >> 5, src = w & 31;
            unsigned long long sel = (slot == 0) ? s0 : ((slot == 1) ? s1 : s2);
            unsigned long long cur = __shfl_sync(0xffffffffu, sel, src);
            int bmax = PRE_NMS - w*64; if (bmax > 64) bmax = 64;
            for (int b = 0; b < bmax; b++) {
                if ((cur >> b) & 1ull) continue;
                int i = w*64 + b;
                float4 bx = sbox[i];
                float h = bx.z - bx.x, wd = bx.w - bx.y;
                if (h < 16.f || wd < 16.f) continue;
                if (L == 0) skeep[kept] = i;
                kept++;
                if (kept == POST_NMS) break;
                const unsigned long long* mrow = g_mask + (size_t)i*NMSB;
                s0 |= mrow[L];
                s1 |= mrow[32 + L];
                if (64 + L < NMSB) s2 |= mrow[64 + L];
                sel = (slot == 0) ? s0 : ((slot == 1) ? s1 : s2);
                cur = __shfl_sync(0xffffffffu, sel, src);
            }
        }
        if (L == 0) s_nk = kept;
    }
    __syncthreads();

    int nk = s_nk;
    for (int s = tid; s < POST_NMS; s += blockDim.x) {
        float4 o = make_float4(0.f, 0.f, 0.f, 0.f);
        if (s < nk) o = sbox[skeep[s]];
        *(float4*)&out_props[(size_t)s*4] = o;
    }
}

// ---------------- launch ----------------
extern "C" void kernel_launch(void* const* d_in, const int* in_sizes, int n_in,
                              void* d_out, int out_size)
{
    const float* feat = (const float*)d_in[1];
    const float* anch = (const float*)d_in[2];
    const float* W1   = (const float*)d_in[3];
    const float* b1   = (const float*)d_in[4];
    const float* Wc   = (const float*)d_in[5];
    const float* bc   = (const float*)d_in[6];
    const float* Wr   = (const float*)d_in[7];
    const float* br   = (const float*)d_in[8];
    float* out = (float*)d_out;

    cudaFuncSetAttribute(conv_mma,     cudaFuncAttributeMaxDynamicSharedMemorySize, SMEM_TOT);
    cudaFuncSetAttribute(heads_kernel, cudaFuncAttributeMaxDynamicSharedMemorySize, 512*45*4);
    cudaFuncSetAttribute(sort_kernel,  cudaFuncAttributeMaxDynamicSharedMemorySize, CAND_CAP*8);
    cudaFuncSetAttribute(nms_sweep,    cudaFuncAttributeMaxDynamicSharedMemorySize, 96000 + POST_NMS*4);

    zero_kernel<<<64, 1024>>>();
    split_x<<<(NPIX*CIN + 255)/256, 256>>>(feat);
    split_w<<<dim3(KTOT/32, COC/32), dim3(32, 8)>>>(W1);
    conv_mma<<<148, 256, SMEM_TOT>>>(b1);
    heads_kernel<<<NPIX/64, 256, 512*45*4>>>(Wc, bc, Wr, br, anch,
                                             out, out + NROW);
    thresh_kernel<<<1, 1024>>>();
    compact_kernel<<<(NROW + 255)/256, 256>>>();
    sort_kernel<<<1, 1024, CAND_CAP*8>>>();
    nms_mask_kernel<<<dim3(NMSB, NMSB), 64>>>();
    nms_sweep<<<1, 1024, 96000 + POST_NMS*4>>>(out + NROW + NROW*4);
}

// round 15
// speedup vs baseline: 1.1886x; 1.1057x over previous
#include <cuda_runtime.h>
#include <cuda_fp16.h>
#include <cstdint>
#include <math.h>

// ---------------- problem constants ----------------
#define HF 100
#define WF 160
#define NPIX (HF*WF)          // 16000
#define CIN 512
#define COC 512
#define NA 9
#define NROW (NPIX*NA)        // 144000
#define PRE_NMS 6000
#define POST_NMS 300
#define IMG_H 1600.0f
#define IMG_W 2560.0f
#define IOU_THR 0.7f
#define CAND_CAP 16384
#define KTOT 4608             // 9 taps * 512 channels
#define NSTG 144              // K stages of 32

// conv tiling: 128(pixels) x 64(oc) tiles, 1000 tiles, persistent 148 CTAs
#define NTILE 1000
#define XT_B 10240            // X tile: 128 rows x 80 B (64B data + 16B pad)
#define WT_B 5120             // W tile: 64 rows x 80 B
#define STAGE_B (3*XT_B + 3*WT_B)   // 46080
#define NBUF 4
#define SMEM_TOT (NBUF*STAGE_B)     // 184320

#define NMSB 94               // ceil(6000/64) mask words per row

// epilogue descale constants (operands pre-scaled by 2^10 each)
#define C0 9.5367431640625e-07f        // 2^-20
#define C1 2.3283064365386963e-10f     // 2^-32
#define C2 5.684341886080802e-14f      // 2^-44

// ---------------- scratch (device globals; no cudaMalloc allowed) ----------------
__device__ __half              g_Xh[NPIX*CIN], g_Xm[NPIX*CIN], g_Xl[NPIX*CIN];
__device__ __half              g_Wh[COC*KTOT], g_Wm[COC*KTOT], g_Wl[COC*KTOT];
__device__ float               g_Y[NPIX*COC];       // conv output (relu'd)
__device__ float4              g_props[NROW];       // clipped proposals y1,x1,y2,x2
__device__ unsigned long long  g_keys[NROW];
__device__ unsigned int        g_hist[65536];
__device__ unsigned int        g_T;
__device__ unsigned long long  g_cand[CAND_CAP];
__device__ int                 g_cnt;
__device__ int                 g_rows[PRE_NMS];
__device__ float4              g_box[PRE_NMS];      // sorted candidate boxes
__device__ unsigned long long  g_mask[PRE_NMS*NMSB];// suppression bitmask

// ---------------- small helpers ----------------
__device__ __forceinline__ uint32_t s2u(const void* p) {
    return (uint32_t)__cvta_generic_to_shared((void*)p);
}
__device__ __forceinline__ void cpa16(uint32_t dst, const void* src, int sz) {
    asm volatile("cp.async.cg.shared.global [%0], [%1], 16, %2;"
                 :: "r"(dst), "l"(src), "r"(sz) : "memory");
}

#define LDSM4(r0,r1,r2,r3,addr) \
    asm volatile("ldmatrix.sync.aligned.m8n8.x4.shared.b16 {%0,%1,%2,%3}, [%4];" \
        : "=r"(r0), "=r"(r1), "=r"(r2), "=r"(r3) : "r"(addr))
#define LDSM2(r0,r1,addr) \
    asm volatile("ldmatrix.sync.aligned.m8n8.x2.shared.b16 {%0,%1}, [%2];" \
        : "=r"(r0), "=r"(r1) : "r"(addr))

#define MMAH(acc, a, b) \
    asm volatile("mma.sync.aligned.m16n8k16.row.col.f32.f16.f16.f32 " \
        "{%0,%1,%2,%3}, {%4,%5,%6,%7}, {%8,%9}, {%0,%1,%2,%3};" \
        : "+f"((acc)[0]), "+f"((acc)[1]), "+f"((acc)[2]), "+f"((acc)[3]) \
        : "r"((a)[0]), "r"((a)[1]), "r"((a)[2]), "r"((a)[3]), \
          "r"((b)[0]), "r"((b)[1]))

// exact 3-way fp16 split of x*1024: X' = h + m/2^12 + l/2^24
__device__ __forceinline__ void split3(float x, __half& h, __half& m, __half& l) {
    float xs = x * 1024.0f;
    h = __float2half_rn(xs);
    float r1 = xs - __half2float(h);
    m = __float2half_rn(r1 * 4096.0f);
    float r2 = r1 - __half2float(m) * (1.0f/4096.0f);
    l = __float2half_rn(r2 * 16777216.0f);
}

// ---------------- zero counters ----------------
__global__ void zero_kernel() {
    int i = blockIdx.x * blockDim.x + threadIdx.x;
    if (i < 65536) g_hist[i] = 0u;
    if (i == 0) g_cnt = 0;
}

// ---------------- prep: split X into 3x fp16 (scaled, exact cover) ----------------
__global__ __launch_bounds__(256) void split_x(const float* __restrict__ X) {
    int i = blockIdx.x * blockDim.x + threadIdx.x;
    if (i < NPIX * CIN) {
        __half h, m, l;
        split3(X[i], h, m, l);
        g_Xh[i] = h; g_Xm[i] = m; g_Xl[i] = l;
    }
}

// ---------------- prep: transpose W [k][n] -> [n][k] + 3x fp16 split ----------------
__global__ void split_w(const float* __restrict__ W1) {
    __shared__ float ts[32][33];
    int kb = blockIdx.x * 32, nb = blockIdx.y * 32;
    int tx = threadIdx.x, ty = threadIdx.y;  // 32 x 8
    for (int r = ty; r < 32; r += 8)
        ts[r][tx] = W1[(size_t)(kb + r) * COC + nb + tx];
    __syncthreads();
    for (int r = ty; r < 32; r += 8) {
        __half h, m, l;
        split3(ts[tx][r], h, m, l);
        size_t o = (size_t)(nb + r) * KTOT + kb + tx;
        g_Wh[o] = h; g_Wm[o] = m; g_Wl[o] = l;
    }
}

// ---------------- conv 3x3: persistent fp16x6 mma.sync implicit GEMM ----------------
// Tile 128(pix) x 64(oc), BK=32, 4-stage cp.async pipeline, 512 threads.
// 16 warps: wm = wid&7 (16-row slice), wn = wid>>3 (32-col half).
// 3 accumulator groups: g0=hh (scale 2^-20), g1=hm+mh (2^-32), g2=hl+mm+lh (2^-44).
__global__ __launch_bounds__(512, 1) void conv_mma(const float* __restrict__ b1) {
    extern __shared__ char smc[];
    uint32_t smem_u = s2u(smc);
    int tid = threadIdx.x;
    int lane = tid & 31, wid = tid >> 5;
    int wm = wid & 7, wn = wid >> 3;
    int lr = lane >> 2, lc = lane & 3;

    // loader mapping: X: all 512 threads, one 16B chunk per level (row=tid>>2, c4=tid&3)
    //                 W: threads 0..255, wrow=tid>>2 (0..63)
    int xrow = tid >> 2, c4 = tid & 3;
    uint32_t xdst = (uint32_t)(xrow * 80 + c4 * 16);
    bool wldr = (tid < 256);
    int wrow = tid >> 2;                     // valid when wldr
    uint32_t wdst = (uint32_t)(wrow * 80 + c4 * 16);

    uint32_t aoff = (uint32_t)((wm*16 + (lane & 15)) * 80 + ((lane >> 4) & 1) * 16);
    uint32_t boff[4];
    #pragma unroll
    for (int nf = 0; nf < 4; nf++)
        boff[nf] = (uint32_t)((wn*32 + nf*8 + (lane & 7)) * 80 + ((lane >> 3) & 1) * 16);

    for (int tile = blockIdx.x; tile < NTILE; tile += gridDim.x) {
        int bn = tile & 7, bm = tile >> 3;
        int n0 = bn * 64;
        int pix = bm * 128 + xrow;
        int py = pix / WF, px = pix % WF;

        float acc0[4][4], acc1[4][4], acc2[4][4];
        #pragma unroll
        for (int b = 0; b < 4; b++)
            #pragma unroll
            for (int c = 0; c < 4; c++) { acc0[b][c] = 0.f; acc1[b][c] = 0.f; acc2[b][c] = 0.f; }

        auto load_stage = [&](int s) {
            uint32_t base = smem_u + (uint32_t)(s % NBUF) * STAGE_B;
            int tap = s >> 4;
            int cb  = (s & 15) << 5;
            int k0  = s << 5;
            int ky = tap / 3 - 1, kx = tap % 3 - 1;
            int hg = py + ky, wg = px + kx;
            bool ok = ((unsigned)hg < HF) && ((unsigned)wg < WF);
            size_t xo = ok ? ((size_t)(hg * WF + wg) * CIN + cb + c4 * 8) : 0;
            int sz = ok ? 16 : 0;
            cpa16(base + 0*XT_B + xdst, g_Xh + xo, sz);
            cpa16(base + 1*XT_B + xdst, g_Xm + xo, sz);
            cpa16(base + 2*XT_B + xdst, g_Xl + xo, sz);
            if (wldr) {
                size_t wo = (size_t)(n0 + wrow) * KTOT + k0 + c4 * 8;
                cpa16(base + 3*XT_B + 0*WT_B + wdst, g_Wh + wo, 16);
                cpa16(base + 3*XT_B + 1*WT_B + wdst, g_Wm + wo, 16);
                cpa16(base + 3*XT_B + 2*WT_B + wdst, g_Wl + wo, 16);
            }
        };

        load_stage(0);
        asm volatile("cp.async.commit_group;" ::: "memory");
        load_stage(1);
        asm volatile("cp.async.commit_group;" ::: "memory");
        load_stage(2);
        asm volatile("cp.async.commit_group;" ::: "memory");

        for (int s = 0; s < NSTG; s++) {
            asm volatile("cp.async.wait_group 2;" ::: "memory");
            __syncthreads();
            if (s + 3 < NSTG) load_stage(s + 3);
            asm volatile("cp.async.commit_group;" ::: "memory");

            uint32_t st = smem_u + (uint32_t)(s % NBUF) * STAGE_B;

            #pragma unroll
            for (int ks = 0; ks < 2; ks++) {
                uint32_t kadd = (uint32_t)(ks * 32);
                uint32_t bf[3][4][2];
                #pragma unroll
                for (int lev = 0; lev < 3; lev++)
                    #pragma unroll
                    for (int nf = 0; nf < 4; nf++)
                        LDSM2(bf[lev][nf][0], bf[lev][nf][1],
                              st + 3*XT_B + lev * WT_B + boff[nf] + kadd);

                // A level h: hh -> g0; hm -> g1; hl -> g2
                {
                    uint32_t af[4];
                    LDSM4(af[0], af[1], af[2], af[3], st + 0*XT_B + aoff + kadd);
                    #pragma unroll
                    for (int nf = 0; nf < 4; nf++) MMAH(acc0[nf], af, bf[0][nf]);
                    #pragma unroll
                    for (int nf = 0; nf < 4; nf++) MMAH(acc1[nf], af, bf[1][nf]);
                    #pragma unroll
                    for (int nf = 0; nf < 4; nf++) MMAH(acc2[nf], af, bf[2][nf]);
                }
                // A level m: mh -> g1; mm -> g2
                {
                    uint32_t af[4];
                    LDSM4(af[0], af[1], af[2], af[3], st + 1*XT_B + aoff + kadd);
                    #pragma unroll
                    for (int nf = 0; nf < 4; nf++) MMAH(acc1[nf], af, bf[0][nf]);
                    #pragma unroll
                    for (int nf = 0; nf < 4; nf++) MMAH(acc2[nf], af, bf[1][nf]);
                }
                // A level l: lh -> g2  (dropped terms <= 2^-36 level)
                {
                    uint32_t af[4];
                    LDSM4(af[0], af[1], af[2], af[3], st + 2*XT_B + aoff + kadd);
                    #pragma unroll
                    for (int nf = 0; nf < 4; nf++) MMAH(acc2[nf], af, bf[0][nf]);
                }
            }
        }

        // epilogue: descale + combine groups, +bias, relu
        {
            int prow = bm*128 + wm*16 + lr;
            #pragma unroll
            for (int nf = 0; nf < 4; nf++) {
                int oc = n0 + wn*32 + nf*8 + 2*lc;
                float2 bb = *(const float2*)&b1[oc];
                float2 v0, v1;
                v0.x = fmaxf(acc0[nf][0]*C0 + acc1[nf][0]*C1 + acc2[nf][0]*C2 + bb.x, 0.f);
                v0.y = fmaxf(acc0[nf][1]*C0 + acc1[nf][1]*C1 + acc2[nf][1]*C2 + bb.y, 0.f);
                v1.x = fmaxf(acc0[nf][2]*C0 + acc1[nf][2]*C1 + acc2[nf][2]*C2 + bb.x, 0.f);
                v1.y = fmaxf(acc0[nf][3]*C0 + acc1[nf][3]*C1 + acc2[nf][3]*C2 + bb.y, 0.f);
                *(float2*)&g_Y[(size_t)prow * COC + oc]       = v0;
                *(float2*)&g_Y[(size_t)(prow + 8) * COC + oc] = v1;
            }
        }
        // buffers 0..2 rewritten by next tile only after the syncs of stages 141..143;
        // buffer 3 rewritten after next tile's s=0 sync. No cross-tile race.
    }
}

// ---------------- heads: 1x1 convs + softmax + decode + keys + hist ----------------
__global__ __launch_bounds__(256) void heads_kernel(
    const float* __restrict__ Wc, const float* __restrict__ bc,
    const float* __restrict__ Wr, const float* __restrict__ br,
    const float* __restrict__ anch,
    float* __restrict__ out_scores, float* __restrict__ out_deltas)
{
    extern __shared__ float sW[];   // [512][45]
    int tid = threadIdx.x;
    for (int i = tid; i < 512*9;  i += blockDim.x) { int c = i/9;  int o = i%9;  sW[c*45 + o]     = Wc[i]; }
    for (int i = tid; i < 512*36; i += blockDim.x) { int c = i/36; int o = i%36; sW[c*45 + 9 + o] = Wr[i]; }
    __syncthreads();

    int warp = tid >> 5, lane = tid & 31;

    for (int it = 0; it < 8; it++) {
        int pix = blockIdx.x*64 + warp*8 + it;
        const float* yrow = g_Y + (size_t)pix*COC;

        float acc[45];
        #pragma unroll
        for (int o = 0; o < 45; o++) acc[o] = 0.f;

        #pragma unroll
        for (int i = 0; i < 16; i++) {
            int c = lane + 32*i;
            float yv = yrow[c];
            const float* w = &sW[c*45];
            #pragma unroll
            for (int o = 0; o < 45; o++) acc[o] += yv * w[o];
        }
        #pragma unroll
        for (int o = 0; o < 45; o++) {
            float v = acc[o];
            v += __shfl_xor_sync(0xffffffffu, v, 16);
            v += __shfl_xor_sync(0xffffffffu, v, 8);
            v += __shfl_xor_sync(0xffffffffu, v, 4);
            v += __shfl_xor_sync(0xffffffffu, v, 2);
            v += __shfl_xor_sync(0xffffffffu, v, 1);
            acc[o] = v;
        }

        if (lane < 9) {
            int a = lane;
            int r = pix*9 + a;
            float lg[9];
            #pragma unroll
            for (int o = 0; o < 9; o++) lg[o] = acc[o] + bc[o];
            float mx = lg[0];
            #pragma unroll
            for (int o = 1; o < 9; o++) mx = fmaxf(mx, lg[o]);
            float den = 0.f;
            #pragma unroll
            for (int o = 0; o < 9; o++) den += expf(lg[o] - mx);
            float score = expf(lg[a] - mx) / den;
            out_scores[r] = score;

            float d0 = acc[9 + 4*a + 0] + br[4*a + 0];
            float d1 = acc[9 + 4*a + 1] + br[4*a + 1];
            float d2 = acc[9 + 4*a + 2] + br[4*a + 2];
            float d3 = acc[9 + 4*a + 3] + br[4*a + 3];
            out_deltas[(size_t)r*4 + 0] = d0;
            out_deltas[(size_t)r*4 + 1] = d1;
            out_deltas[(size_t)r*4 + 2] = d2;
            out_deltas[(size_t)r*4 + 3] = d3;

            float4 an = ((const float4*)anch)[r];   // cy,cx,h,w
            float cy = an.x + d0*an.z;
            float cx = an.y + d1*an.w;
            float sy = an.z * expf(d2);
            float sx = an.w * expf(d3);
            float y1 = fmaxf(cy - 0.5f*sy, 0.f);
            float x1 = fmaxf(cx - 0.5f*sx, 0.f);
            float y2 = fminf(cy + 0.5f*sy, IMG_H);
            float x2 = fminf(cx + 0.5f*sx, IMG_W);
            g_props[r] = make_float4(y1, x1, y2, x2);

            unsigned sb = __float_as_uint(score);
            g_keys[r] = ((unsigned long long)sb << 32) | (0xFFFFFFFFu - (unsigned)r);
            atomicAdd(&g_hist[sb >> 16], 1u);
        }
    }
}

// ---------------- threshold: vectorized hist sums + block scan ----------------
__global__ __launch_bounds__(1024) void thresh_kernel() {
    __shared__ unsigned wsum[32];
    int t = threadIdx.x;
    int hi = 65535 - t*64;
    const uint4* p = (const uint4*)(g_hist + (hi - 63));
    unsigned s = 0;
    #pragma unroll
    for (int q = 0; q < 16; q++) { uint4 v = p[q]; s += v.x + v.y + v.z + v.w; }

    unsigned c = s;
    #pragma unroll
    for (int o = 1; o < 32; o <<= 1) {
        unsigned n = __shfl_up_sync(0xffffffffu, c, o);
        if ((t & 31) >= o) c += n;
    }
    if ((t & 31) == 31) wsum[t >> 5] = c;
    __syncthreads();
    if (t < 32) {
        unsigned wv = wsum[t];
        #pragma unroll
        for (int o = 1; o < 32; o <<= 1) {
            unsigned n = __shfl_up_sync(0xffffffffu, wv, o);
            if (t >= o) wv += n;
        }
        wsum[t] = wv;
    }
    __syncthreads();
    unsigned pre = (t >> 5) ? wsum[(t >> 5) - 1] : 0u;
    unsigned C = c + pre;
    unsigned E = C - s;
    if (E < PRE_NMS && C >= PRE_NMS) {
        unsigned cum = E;
        unsigned T = (unsigned)(hi - 63);
        for (int b = 0; b < 64; b++) {
            cum += g_hist[hi - b];
            if (cum >= PRE_NMS) { T = (unsigned)(hi - b); break; }
        }
        g_T = T;
    }
}

// ---------------- compact candidates with bin >= T ----------------
__global__ void compact_kernel() {
    int r = blockIdx.x*blockDim.x + threadIdx.x;
    if (r >= NROW) return;
    unsigned long long k = g_keys[r];
    if ((unsigned)(k >> 48) >= g_T) {
        int p = atomicAdd(&g_cnt, 1);
        if (p < CAND_CAP) g_cand[p] = k;
    }
}

// ---------------- one-block bitonic sort (descending) + gather ----------------
__global__ __launch_bounds__(1024) void sort_kernel() {
    extern __shared__ unsigned long long sk[];   // 16384 * 8 = 128 KB
    int n = g_cnt; if (n > CAND_CAP) n = CAND_CAP;
    for (int i = threadIdx.x; i < CAND_CAP; i += 1024)
        sk[i] = (i < n) ? g_cand[i] : 0ULL;
    __syncthreads();

    for (int k = 2; k <= CAND_CAP; k <<= 1) {
        for (int j = k >> 1; j > 0; j >>= 1) {
            for (int i = threadIdx.x; i < CAND_CAP; i += 1024) {
                int ixj = i ^ j;
                if (ixj > i) {
                    unsigned long long a = sk[i], b = sk[ixj];
                    bool descBlock = ((i & k) == 0);
                    bool doSwap = descBlock ? (a < b) : (a > b);
                    if (doSwap) { sk[i] = b; sk[ixj] = a; }
                }
            }
            __syncthreads();
        }
    }
    for (int i = threadIdx.x; i < PRE_NMS; i += 1024) {
        int r = (int)(0xFFFFFFFFu - (unsigned)(sk[i] & 0xFFFFFFFFULL));
        g_rows[i] = r;
        g_box[i] = g_props[r];
    }
}

// ---------------- NMS phase A: suppression bitmask (i suppresses j>i) ----------------
__global__ __launch_bounds__(64) void nms_mask_kernel() {
    int bi = blockIdx.y, bj = blockIdx.x;
    int t = threadIdx.x;
    int i = bi*64 + t;
    if (bj < bi) {
        if (i < PRE_NMS) g_mask[(size_t)i*NMSB + bj] = 0ull;
        return;
    }
    __shared__ float4 jb[64];
    int j0 = bj*64 + t;
    jb[t] = (j0 < PRE_NMS) ? g_box[j0] : make_float4(0.f,0.f,0.f,0.f);
    __syncthreads();
    if (i >= PRE_NMS) return;
    float4 a = g_box[i];
    float aarea = (a.z - a.x) * (a.w - a.y);
    unsigned long long bits = 0ull;
    #pragma unroll 4
    for (int jj = 0; jj < 64; jj++) {
        int j = bj*64 + jj;
        if (j <= i) continue;
        float4 c = jb[jj];
        float iy1 = fmaxf(a.x, c.x), ix1 = fmaxf(a.y, c.y);
        float iy2 = fminf(a.z, c.z), ix2 = fminf(a.w, c.w);
        float inter = fmaxf(iy2 - iy1, 0.f) * fmaxf(ix2 - ix1, 0.f);
        float carea = (c.z - c.x) * (c.w - c.y);
        if (inter > IOU_THR * (aarea + carea - inter + 1e-8f)) bits |= (1ull << jj);
    }
    g_mask[(size_t)i*NMSB + bj] = bits;
}

// ---------------- NMS phase B: single-warp sweep over bitmask ----------------
__global__ __launch_bounds__(1024) void nms_sweep(float* __restrict__ out_props) {
    extern __shared__ unsigned char smem[];
    float4* sbox = (float4*)smem;                 // 6000 * 16 = 96000 B
    int* skeep = (int*)(smem + 96000);            // 300 ints
    __shared__ int s_nk;

    int tid = threadIdx.x;
    for (int i = tid; i < PRE_NMS; i += blockDim.x)
        sbox[i] = g_box[i];
    __syncthreads();

    if (tid < 32) {
        int L = tid;
        unsigned long long s0 = 0ull, s1 = 0ull, s2 = 0ull;
        int kept = 0;
        for (int w = 0; w < NMSB && kept < POST_NMS; w++) {
            int slot = w >> 5, src = w & 31;
            unsigned long long sel = (slot == 0) ? s0 : ((slot == 1) ? s1 : s2);
            unsigned long long cur = __shfl_sync(0xffffffffu, sel, src);
            int bmax = PRE_NMS - w*64; if (bmax > 64) bmax = 64;
            for (int b = 0; b < bmax; b++) {
                if ((cur >> b) & 1ull) continue;
                int i = w*64 + b;
                float4 bx = sbox[i];
                float h = bx.z - bx.x, wd = bx.w - bx.y;
                if (h < 16.f || wd < 16.f) continue;
                if (L == 0) skeep[kept] = i;
                kept++;
                if (kept == POST_NMS) break;
                const unsigned long long* mrow = g_mask + (size_t)i*NMSB;
                s0 |= mrow[L];
                s1 |= mrow[32 + L];
                if (64 + L < NMSB) s2 |= mrow[64 + L];
                sel = (slot == 0) ? s0 : ((slot == 1) ? s1 : s2);
                cur = __shfl_sync(0xffffffffu, sel, src);
            }
        }
        if (L == 0) s_nk = kept;
    }
    __syncthreads();

    int nk = s_nk;
    for (int s = tid; s < POST_NMS; s += blockDim.x) {
        float4 o = make_float4(0.f, 0.f, 0.f, 0.f);
        if (s < nk) o = sbox[skeep[s]];
        *(float4*)&out_props[(size_t)s*4] = o;
    }
}

// ---------------- launch ----------------
extern "C" void kernel_launch(void* const* d_in, const int* in_sizes, int n_in,
                              void* d_out, int out_size)
{
    const float* feat = (const float*)d_in[1];
    const float* anch = (const float*)d_in[2];
    const float* W1   = (const float*)d_in[3];
    const float* b1   = (const float*)d_in[4];
    const float* Wc   = (const float*)d_in[5];
    const float* bc   = (const float*)d_in[6];
    const float* Wr   = (const float*)d_in[7];
    const float* br   = (const float*)d_in[8];
    float* out = (float*)d_out;

    cudaFuncSetAttribute(conv_mma,     cudaFuncAttributeMaxDynamicSharedMemorySize, SMEM_TOT);
    cudaFuncSetAttribute(heads_kernel, cudaFuncAttributeMaxDynamicSharedMemorySize, 512*45*4);
    cudaFuncSetAttribute(sort_kernel,  cudaFuncAttributeMaxDynamicSharedMemorySize, CAND_CAP*8);
    cudaFuncSetAttribute(nms_sweep,    cudaFuncAttributeMaxDynamicSharedMemorySize, 96000 + POST_NMS*4);

    zero_kernel<<<64, 1024>>>();
    split_x<<<(NPIX*CIN + 255)/256, 256>>>(feat);
    split_w<<<dim3(KTOT/32, COC/32), dim3(32, 8)>>>(W1);
    conv_mma<<<148, 512, SMEM_TOT>>>(b1);
    heads_kernel<<<NPIX/64, 256, 512*45*4>>>(Wc, bc, Wr, br, anch,
                                             out, out + NROW);
    thresh_kernel<<<1, 1024>>>();
    compact_kernel<<<(NROW + 255)/256, 256>>>();
    sort_kernel<<<1, 1024, CAND_CAP*8>>>();
    nms_mask_kernel<<<dim3(NMSB, NMSB), 64>>>();
    nms_sweep<<<1, 1024, 96000 + POST_NMS*4>>>(out + NROW + NROW*4);
}

// round 16
// speedup vs baseline: 1.5440x; 1.2990x over previous
#include <cuda_runtime.h>
#include <cuda_fp16.h>
#include <cstdint>
#include <math.h>

// ---------------- problem constants ----------------
#define HF 100
#define WF 160
#define NPIX (HF*WF)          // 16000
#define CIN 512
#define COC 512
#define NA 9
#define NROW (NPIX*NA)        // 144000
#define PRE_NMS 6000
#define POST_NMS 300
#define IMG_H 1600.0f
#define IMG_W 2560.0f
#define IOU_THR 0.7f
#define CAND_CAP 16384
#define KTOT 4608             // 9 taps * 512 channels
#define NSTG 72               // K stages of 64

// conv tiling: 128(pixels) x 64(oc) tiles, 1000 tiles, persistent 148 CTAs
// BK=64: X tile 128 rows x 128 B (swizzled, no pad), W tile 64 rows x 128 B
#define NTILE 1000
#define XT_B 16384            // 128 * 128
#define WT_B 8192             // 64 * 128
#define STAGE_B (3*XT_B + 3*WT_B)   // 73728
#define NBUF 3
#define SMEM_TOT (NBUF*STAGE_B)     // 221184

#define NMSB 94               // ceil(6000/64) mask words per row

// epilogue descale constants (operands pre-scaled by 2^10 each)
#define C0 9.5367431640625e-07f        // 2^-20
#define C1 2.3283064365386963e-10f     // 2^-32
#define C2 5.684341886080802e-14f      // 2^-44

// ---------------- scratch (device globals; no cudaMalloc allowed) ----------------
__device__ __half              g_Xh[NPIX*CIN], g_Xm[NPIX*CIN], g_Xl[NPIX*CIN];
__device__ __half              g_Wh[COC*KTOT], g_Wm[COC*KTOT], g_Wl[COC*KTOT];
__device__ float               g_Y[NPIX*COC];       // conv output (relu'd)
__device__ float4              g_props[NROW];       // clipped proposals y1,x1,y2,x2
__device__ unsigned long long  g_keys[NROW];
__device__ unsigned int        g_hist[65536];
__device__ unsigned int        g_T;
__device__ unsigned long long  g_cand[CAND_CAP];
__device__ int                 g_cnt;
__device__ int                 g_rows[PRE_NMS];
__device__ float4              g_box[PRE_NMS];      // sorted candidate boxes
__device__ unsigned long long  g_mask[PRE_NMS*NMSB];// suppression bitmask

// ---------------- small helpers ----------------
__device__ __forceinline__ uint32_t s2u(const void* p) {
    return (uint32_t)__cvta_generic_to_shared((void*)p);
}
__device__ __forceinline__ void cpa16(uint32_t dst, const void* src, int sz) {
    asm volatile("cp.async.cg.shared.global [%0], [%1], 16, %2;"
                 :: "r"(dst), "l"(src), "r"(sz) : "memory");
}

#define LDSM4(r0,r1,r2,r3,addr) \
    asm volatile("ldmatrix.sync.aligned.m8n8.x4.shared.b16 {%0,%1,%2,%3}, [%4];" \
        : "=r"(r0), "=r"(r1), "=r"(r2), "=r"(r3) : "r"(addr))
#define LDSM2(r0,r1,addr) \
    asm volatile("ldmatrix.sync.aligned.m8n8.x2.shared.b16 {%0,%1}, [%2];" \
        : "=r"(r0), "=r"(r1) : "r"(addr))

#define MMAH(acc, a, b) \
    asm volatile("mma.sync.aligned.m16n8k16.row.col.f32.f16.f16.f32 " \
        "{%0,%1,%2,%3}, {%4,%5,%6,%7}, {%8,%9}, {%0,%1,%2,%3};" \
        : "+f"((acc)[0]), "+f"((acc)[1]), "+f"((acc)[2]), "+f"((acc)[3]) \
        : "r"((a)[0]), "r"((a)[1]), "r"((a)[2]), "r"((a)[3]), \
          "r"((b)[0]), "r"((b)[1]))

// exact 3-way fp16 split of x*1024: X' = h + m/2^12 + l/2^24
__device__ __forceinline__ void split3(float x, __half& h, __half& m, __half& l) {
    float xs = x * 1024.0f;
    h = __float2half_rn(xs);
    float r1 = xs - __half2float(h);
    m = __float2half_rn(r1 * 4096.0f);
    float r2 = r1 - __half2float(m) * (1.0f/4096.0f);
    l = __float2half_rn(r2 * 16777216.0f);
}

// ---------------- zero counters ----------------
__global__ void zero_kernel() {
    int i = blockIdx.x * blockDim.x + threadIdx.x;
    if (i < 65536) g_hist[i] = 0u;
    if (i == 0) g_cnt = 0;
}

// ---------------- prep: split X into 3x fp16 (scaled, exact cover) ----------------
__global__ __launch_bounds__(256) void split_x(const float* __restrict__ X) {
    int i = blockIdx.x * blockDim.x + threadIdx.x;
    if (i < NPIX * CIN) {
        __half h, m, l;
        split3(X[i], h, m, l);
        g_Xh[i] = h; g_Xm[i] = m; g_Xl[i] = l;
    }
}

// ---------------- prep: transpose W [k][n] -> [n][k] + 3x fp16 split ----------------
__global__ void split_w(const float* __restrict__ W1) {
    __shared__ float ts[32][33];
    int kb = blockIdx.x * 32, nb = blockIdx.y * 32;
    int tx = threadIdx.x, ty = threadIdx.y;  // 32 x 8
    for (int r = ty; r < 32; r += 8)
        ts[r][tx] = W1[(size_t)(kb + r) * COC + nb + tx];
    __syncthreads();
    for (int r = ty; r < 32; r += 8) {
        __half h, m, l;
        split3(ts[tx][r], h, m, l);
        size_t o = (size_t)(nb + r) * KTOT + kb + tx;
        g_Wh[o] = h; g_Wm[o] = m; g_Wl[o] = l;
    }
}

// ---------------- conv 3x3: persistent fp16x6 mma.sync implicit GEMM ----------------
// Tile 128(pix) x 64(oc), BK=64, 3-buf cp.async pipeline, 512 threads, 1 sync/stage.
// 16 warps: wm = wid&7 (16-row slice), wn = wid>>3 (32-col half).
// SMEM rows are 128 B with XOR-8 chunk swizzle (chunk ^= row&7) — conflict-free ldmatrix.
// 3 accumulator groups: g0=hh (2^-20), g1=hm+mh (2^-32), g2=hl+mm+lh (2^-44).
__global__ __launch_bounds__(512, 1) void conv_mma(const float* __restrict__ b1) {
    extern __shared__ char smc[];
    uint32_t smem_u = s2u(smc);
    int tid = threadIdx.x;
    int lane = tid & 31, wid = tid >> 5;
    int wm = wid & 7, wn = wid >> 3;
    int lr = lane >> 2, lc = lane & 3;

    // loader mapping: X: 1024 chunks (128 rows x 8), all 512 threads x2
    //                 W: 512 chunks (64 rows x 8), threads 0..255 x2
    int xr0 = tid >> 3, xc8 = tid & 7;         // rows xr0 and xr0+64
    uint32_t xd0 = (uint32_t)(xr0 * 128 + ((xc8 ^ (xr0 & 7)) << 4));
    uint32_t xd1 = (uint32_t)((xr0 + 64) * 128 + ((xc8 ^ ((xr0 + 64) & 7)) << 4));
    bool wldr = (tid < 256);
    int wr0 = tid >> 3;                         // rows wr0 and wr0+32 (valid if wldr)
    uint32_t wd0 = (uint32_t)(wr0 * 128 + ((xc8 ^ (wr0 & 7)) << 4));
    uint32_t wd1 = (uint32_t)((wr0 + 32) * 128 + ((xc8 ^ ((wr0 + 32) & 7)) << 4));

    // fragment addressing (swizzled): row base + ((chunk ^ (row&7))<<4)
    int arow = wm*16 + (lane & 15);
    uint32_t abase = (uint32_t)(arow * 128);
    int asel = (lane >> 4) & 1, axor = arow & 7;
    int brow[4]; uint32_t bbase[4]; int bxor[4];
    int bsel = (lane >> 3) & 1;
    #pragma unroll
    for (int nf = 0; nf < 4; nf++) {
        brow[nf] = wn*32 + nf*8 + (lane & 7);
        bbase[nf] = (uint32_t)(brow[nf] * 128);
        bxor[nf] = brow[nf] & 7;
    }

    for (int tile = blockIdx.x; tile < NTILE; tile += gridDim.x) {
        int bn = tile & 7, bm = tile >> 3;
        int n0 = bn * 64;
        int pix0 = bm * 128 + xr0;
        int py0 = pix0 / WF, px0 = pix0 % WF;
        int pix1 = pix0 + 64;
        int py1 = pix1 / WF, px1 = pix1 % WF;

        float acc0[4][4], acc1[4][4], acc2[4][4];
        #pragma unroll
        for (int b = 0; b < 4; b++)
            #pragma unroll
            for (int c = 0; c < 4; c++) { acc0[b][c] = 0.f; acc1[b][c] = 0.f; acc2[b][c] = 0.f; }

        auto load_stage = [&](int s) {
            uint32_t base = smem_u + (uint32_t)(s % NBUF) * STAGE_B;
            int tap = s >> 3;                 // 8 stages per tap
            int cb  = (s & 7) << 6;           // channel base within tap
            int k0  = s << 6;                 // global K base (for W)
            int ky = tap / 3 - 1, kx = tap % 3 - 1;
            int hg0 = py0 + ky, wg0 = px0 + kx;
            int hg1 = py1 + ky, wg1 = px1 + kx;
            bool ok0 = ((unsigned)hg0 < HF) && ((unsigned)wg0 < WF);
            bool ok1 = ((unsigned)hg1 < HF) && ((unsigned)wg1 < WF);
            size_t xo0 = ok0 ? ((size_t)(hg0 * WF + wg0) * CIN + cb + xc8 * 8) : 0;
            size_t xo1 = ok1 ? ((size_t)(hg1 * WF + wg1) * CIN + cb + xc8 * 8) : 0;
            int sz0 = ok0 ? 16 : 0, sz1 = ok1 ? 16 : 0;
            cpa16(base + 0*XT_B + xd0, g_Xh + xo0, sz0);
            cpa16(base + 0*XT_B + xd1, g_Xh + xo1, sz1);
            cpa16(base + 1*XT_B + xd0, g_Xm + xo0, sz0);
            cpa16(base + 1*XT_B + xd1, g_Xm + xo1, sz1);
            cpa16(base + 2*XT_B + xd0, g_Xl + xo0, sz0);
            cpa16(base + 2*XT_B + xd1, g_Xl + xo1, sz1);
            if (wldr) {
                size_t wo0 = (size_t)(n0 + wr0) * KTOT + k0 + xc8 * 8;
                size_t wo1 = (size_t)(n0 + wr0 + 32) * KTOT + k0 + xc8 * 8;
                cpa16(base + 3*XT_B + 0*WT_B + wd0, g_Wh + wo0, 16);
                cpa16(base + 3*XT_B + 0*WT_B + wd1, g_Wh + wo1, 16);
                cpa16(base + 3*XT_B + 1*WT_B + wd0, g_Wm + wo0, 16);
                cpa16(base + 3*XT_B + 1*WT_B + wd1, g_Wm + wo1, 16);
                cpa16(base + 3*XT_B + 2*WT_B + wd0, g_Wl + wo0, 16);
                cpa16(base + 3*XT_B + 2*WT_B + wd1, g_Wl + wo1, 16);
            }
        };

        load_stage(0);
        asm volatile("cp.async.commit_group;" ::: "memory");
        load_stage(1);
        asm volatile("cp.async.commit_group;" ::: "memory");

        for (int s = 0; s < NSTG; s++) {
            asm volatile("cp.async.wait_group 1;" ::: "memory");
            __syncthreads();
            if (s + 2 < NSTG) load_stage(s + 2);
            asm volatile("cp.async.commit_group;" ::: "memory");   // always commit

            uint32_t st = smem_u + (uint32_t)(s % NBUF) * STAGE_B;

            #pragma unroll
            for (int ks = 0; ks < 4; ks++) {
                int ach = (2*ks + asel) ^ axor;
                uint32_t aadd = abase + (uint32_t)(ach << 4);
                uint32_t bf[3][4][2];
                #pragma unroll
                for (int lev = 0; lev < 3; lev++)
                    #pragma unroll
                    for (int nf = 0; nf < 4; nf++) {
                        int bch = (2*ks + bsel) ^ bxor[nf];
                        LDSM2(bf[lev][nf][0], bf[lev][nf][1],
                              st + 3*XT_B + lev * WT_B + bbase[nf] + (uint32_t)(bch << 4));
                    }

                // A level h: hh -> g0; hm -> g1; hl -> g2
                {
                    uint32_t af[4];
                    LDSM4(af[0], af[1], af[2], af[3], st + 0*XT_B + aadd);
                    #pragma unroll
                    for (int nf = 0; nf < 4; nf++) MMAH(acc0[nf], af, bf[0][nf]);
                    #pragma unroll
                    for (int nf = 0; nf < 4; nf++) MMAH(acc1[nf], af, bf[1][nf]);
                    #pragma unroll
                    for (int nf = 0; nf < 4; nf++) MMAH(acc2[nf], af, bf[2][nf]);
                }
                // A level m: mh -> g1; mm -> g2
                {
                    uint32_t af[4];
                    LDSM4(af[0], af[1], af[2], af[3], st + 1*XT_B + aadd);
                    #pragma unroll
                    for (int nf = 0; nf < 4; nf++) MMAH(acc1[nf], af, bf[0][nf]);
                    #pragma unroll
                    for (int nf = 0; nf < 4; nf++) MMAH(acc2[nf], af, bf[1][nf]);
                }
                // A level l: lh -> g2  (dropped terms <= 2^-36 level)
                {
                    uint32_t af[4];
                    LDSM4(af[0], af[1], af[2], af[3], st + 2*XT_B + aadd);
                    #pragma unroll
                    for (int nf = 0; nf < 4; nf++) MMAH(acc2[nf], af, bf[0][nf]);
                }
            }
        }

        // epilogue: descale + combine groups, +bias, relu
        {
            int prow = bm*128 + wm*16 + lr;
            #pragma unroll
            for (int nf = 0; nf < 4; nf++) {
                int oc = n0 + wn*32 + nf*8 + 2*lc;
                float2 bb = *(const float2*)&b1[oc];
                float2 v0, v1;
                v0.x = fmaxf(acc0[nf][0]*C0 + acc1[nf][0]*C1 + acc2[nf][0]*C2 + bb.x, 0.f);
                v0.y = fmaxf(acc0[nf][1]*C0 + acc1[nf][1]*C1 + acc2[nf][1]*C2 + bb.y, 0.f);
                v1.x = fmaxf(acc0[nf][2]*C0 + acc1[nf][2]*C1 + acc2[nf][2]*C2 + bb.x, 0.f);
                v1.y = fmaxf(acc0[nf][3]*C0 + acc1[nf][3]*C1 + acc2[nf][3]*C2 + bb.y, 0.f);
                *(float2*)&g_Y[(size_t)prow * COC + oc]       = v0;
                *(float2*)&g_Y[(size_t)(prow + 8) * COC + oc] = v1;
            }
        }
        // cross-tile smem safety: buf0 last read at stage 69 (syncs at 70,71 follow);
        // buf1 last read at 70 (sync at 71 follows); buf2 last read at 71, and next
        // tile's first overwrite of buf2 happens only after next-tile s=0's sync.
    }
}

// ---------------- heads: 1x1 convs + softmax + decode + keys + hist ----------------
__global__ __launch_bounds__(256) void heads_kernel(
    const float* __restrict__ Wc, const float* __restrict__ bc,
    const float* __restrict__ Wr, const float* __restrict__ br,
    const float* __restrict__ anch,
    float* __restrict__ out_scores, float* __restrict__ out_deltas)
{
    extern __shared__ float sW[];   // [512][45]
    int tid = threadIdx.x;
    for (int i = tid; i < 512*9;  i += blockDim.x) { int c = i/9;  int o = i%9;  sW[c*45 + o]     = Wc[i]; }
    for (int i = tid; i < 512*36; i += blockDim.x) { int c = i/36; int o = i%36; sW[c*45 + 9 + o] = Wr[i]; }
    __syncthreads();

    int warp = tid >> 5, lane = tid & 31;

    for (int it = 0; it < 8; it++) {
        int pix = blockIdx.x*64 + warp*8 + it;
        const float* yrow = g_Y + (size_t)pix*COC;

        float acc[45];
        #pragma unroll
        for (int o = 0; o < 45; o++) acc[o] = 0.f;

        #pragma unroll
        for (int i = 0; i < 16; i++) {
            int c = lane + 32*i;
            float yv = yrow[c];
            const float* w = &sW[c*45];
            #pragma unroll
            for (int o = 0; o < 45; o++) acc[o] += yv * w[o];
        }
        #pragma unroll
        for (int o = 0; o < 45; o++) {
            float v = acc[o];
            v += __shfl_xor_sync(0xffffffffu, v, 16);
            v += __shfl_xor_sync(0xffffffffu, v, 8);
            v += __shfl_xor_sync(0xffffffffu, v, 4);
            v += __shfl_xor_sync(0xffffffffu, v, 2);
            v += __shfl_xor_sync(0xffffffffu, v, 1);
            acc[o] = v;
        }

        if (lane < 9) {
            int a = lane;
            int r = pix*9 + a;
            float lg[9];
            #pragma unroll
            for (int o = 0; o < 9; o++) lg[o] = acc[o] + bc[o];
            float mx = lg[0];
            #pragma unroll
            for (int o = 1; o < 9; o++) mx = fmaxf(mx, lg[o]);
            float den = 0.f;
            #pragma unroll
            for (int o = 0; o < 9; o++) den += expf(lg[o] - mx);
            float score = expf(lg[a] - mx) / den;
            out_scores[r] = score;

            float d0 = acc[9 + 4*a + 0] + br[4*a + 0];
            float d1 = acc[9 + 4*a + 1] + br[4*a + 1];
            float d2 = acc[9 + 4*a + 2] + br[4*a + 2];
            float d3 = acc[9 + 4*a + 3] + br[4*a + 3];
            out_deltas[(size_t)r*4 + 0] = d0;
            out_deltas[(size_t)r*4 + 1] = d1;
            out_deltas[(size_t)r*4 + 2] = d2;
            out_deltas[(size_t)r*4 + 3] = d3;

            float4 an = ((const float4*)anch)[r];   // cy,cx,h,w
            float cy = an.x + d0*an.z;
            float cx = an.y + d1*an.w;
            float sy = an.z * expf(d2);
            float sx = an.w * expf(d3);
            float y1 = fmaxf(cy - 0.5f*sy, 0.f);
            float x1 = fmaxf(cx - 0.5f*sx, 0.f);
            float y2 = fminf(cy + 0.5f*sy, IMG_H);
            float x2 = fminf(cx + 0.5f*sx, IMG_W);
            g_props[r] = make_float4(y1, x1, y2, x2);

            unsigned sb = __float_as_uint(score);
            g_keys[r] = ((unsigned long long)sb << 32) | (0xFFFFFFFFu - (unsigned)r);
            atomicAdd(&g_hist[sb >> 16], 1u);
        }
    }
}

// ---------------- threshold: vectorized hist sums + block scan ----------------
__global__ __launch_bounds__(1024) void thresh_kernel() {
    __shared__ unsigned wsum[32];
    int t = threadIdx.x;
    int hi = 65535 - t*64;
    const uint4* p = (const uint4*)(g_hist + (hi - 63));
    unsigned s = 0;
    #pragma unroll
    for (int q = 0; q < 16; q++) { uint4 v = p[q]; s += v.x + v.y + v.z + v.w; }

    unsigned c = s;
    #pragma unroll
    for (int o = 1; o < 32; o <<= 1) {
        unsigned n = __shfl_up_sync(0xffffffffu, c, o);
        if ((t & 31) >= o) c += n;
    }
    if ((t & 31) == 31) wsum[t >> 5] = c;
    __syncthreads();
    if (t < 32) {
        unsigned wv = wsum[t];
        #pragma unroll
        for (int o = 1; o < 32; o <<= 1) {
            unsigned n = __shfl_up_sync(0xffffffffu, wv, o);
            if (t >= o) wv += n;
        }
        wsum[t] = wv;
    }
    __syncthreads();
    unsigned pre = (t >> 5) ? wsum[(t >> 5) - 1] : 0u;
    unsigned C = c + pre;
    unsigned E = C - s;
    if (E < PRE_NMS && C >= PRE_NMS) {
        unsigned cum = E;
        unsigned T = (unsigned)(hi - 63);
        for (int b = 0; b < 64; b++) {
            cum += g_hist[hi - b];
            if (cum >= PRE_NMS) { T = (unsigned)(hi - b); break; }
        }
        g_T = T;
    }
}

// ---------------- compact candidates with bin >= T ----------------
__global__ void compact_kernel() {
    int r = blockIdx.x*blockDim.x + threadIdx.x;
    if (r >= NROW) return;
    unsigned long long k = g_keys[r];
    if ((unsigned)(k >> 48) >= g_T) {
        int p = atomicAdd(&g_cnt, 1);
        if (p < CAND_CAP) g_cand[p] = k;
    }
}

// ---------------- one-block bitonic sort (descending) + gather ----------------
// Sorts 8192 when the candidate count allows, else 16384.
__global__ __launch_bounds__(1024) void sort_kernel() {
    extern __shared__ unsigned long long sk[];   // up to 16384 * 8 = 128 KB
    int n = g_cnt; if (n > CAND_CAP) n = CAND_CAP;
    int SZ = (n <= 8192) ? 8192 : CAND_CAP;
    for (int i = threadIdx.x; i < SZ; i += 1024)
        sk[i] = (i < n) ? g_cand[i] : 0ULL;
    __syncthreads();

    for (int k = 2; k <= SZ; k <<= 1) {
        for (int j = k >> 1; j > 0; j >>= 1) {
            for (int i = threadIdx.x; i < SZ; i += 1024) {
                int ixj = i ^ j;
                if (ixj > i) {
                    unsigned long long a = sk[i], b = sk[ixj];
                    bool descBlock = ((i & k) == 0);
                    bool doSwap = descBlock ? (a < b) : (a > b);
                    if (doSwap) { sk[i] = b; sk[ixj] = a; }
                }
            }
            __syncthreads();
        }
    }
    for (int i = threadIdx.x; i < PRE_NMS; i += 1024) {
        int r = (int)(0xFFFFFFFFu - (unsigned)(sk[i] & 0xFFFFFFFFULL));
        g_rows[i] = r;
        g_box[i] = g_props[r];
    }
}

// ---------------- NMS phase A: suppression bitmask (i suppresses j>i) ----------------
__global__ __launch_bounds__(64) void nms_mask_kernel() {
    int bi = blockIdx.y, bj = blockIdx.x;
    int t = threadIdx.x;
    int i = bi*64 + t;
    if (bj < bi) {
        if (i < PRE_NMS) g_mask[(size_t)i*NMSB + bj] = 0ull;
        return;
    }
    __shared__ float4 jb[64];
    int j0 = bj*64 + t;
    jb[t] = (j0 < PRE_NMS) ? g_box[j0] : make_float4(0.f,0.f,0.f,0.f);
    __syncthreads();
    if (i >= PRE_NMS) return;
    float4 a = g_box[i];
    float aarea = (a.z - a.x) * (a.w - a.y);
    unsigned long long bits = 0ull;
    #pragma unroll 4
    for (int jj = 0; jj < 64; jj++) {
        int j = bj*64 + jj;
        if (j <= i) continue;
        float4 c = jb[jj];
        float iy1 = fmaxf(a.x, c.x), ix1 = fmaxf(a.y, c.y);
        float iy2 = fminf(a.z, c.z), ix2 = fminf(a.w, c.w);
        float inter = fmaxf(iy2 - iy1, 0.f) * fmaxf(ix2 - ix1, 0.f);
        float carea = (c.z - c.x) * (c.w - c.y);
        if (inter > IOU_THR * (aarea + carea - inter + 1e-8f)) bits |= (1ull << jj);
    }
    g_mask[(size_t)i*NMSB + bj] = bits;
}

// ---------------- NMS phase B: single-warp sweep over bitmask ----------------
__global__ __launch_bounds__(1024) void nms_sweep(float* __restrict__ out_props) {
    extern __shared__ unsigned char smem[];
    float4* sbox = (float4*)smem;                 // 6000 * 16 = 96000 B
    int* skeep = (int*)(smem + 96000);            // 300 ints
    __shared__ int s_nk;

    int tid = threadIdx.x;
    for (int i = tid; i < PRE_NMS; i += blockDim.x)
        sbox[i] = g_box[i];
    __syncthreads();

    if (tid < 32) {
        int L = tid;
        unsigned long long s0 = 0ull, s1 = 0ull, s2 = 0ull;
        int kept = 0;
        for (int w = 0; w < NMSB && kept < POST_NMS; w++) {
            int slot = w >> 5, src = w & 31;
            unsigned long long sel = (slot == 0) ? s0 : ((slot == 1) ? s1 : s2);
            unsigned long long cur = __shfl_sync(0xffffffffu, sel, src);
            int bmax = PRE_NMS - w*64; if (bmax > 64) bmax = 64;
            for (int b = 0; b < bmax; b++) {
                if ((cur >> b) & 1ull) continue;
                int i = w*64 + b;
                float4 bx = sbox[i];
                float h = bx.z - bx.x, wd = bx.w - bx.y;
                if (h < 16.f || wd < 16.f) continue;
                if (L == 0) skeep[kept] = i;
                kept++;
                if (kept == POST_NMS) break;
                const unsigned long long* mrow = g_mask + (size_t)i*NMSB;
                s0 |= mrow[L];
                s1 |= mrow[32 + L];
                if (64 + L < NMSB) s2 |= mrow[64 + L];
                sel = (slot == 0) ? s0 : ((slot == 1) ? s1 : s2);
                cur = __shfl_sync(0xffffffffu, sel, src);
            }
        }
        if (L == 0) s_nk = kept;
    }
    __syncthreads();

    int nk = s_nk;
    for (int s = tid; s < POST_NMS; s += blockDim.x) {
        float4 o = make_float4(0.f, 0.f, 0.f, 0.f);
        if (s < nk) o = sbox[skeep[s]];
        *(float4*)&out_props[(size_t)s*4] = o;
    }
}

// ---------------- launch ----------------
extern "C" void kernel_launch(void* const* d_in, const int* in_sizes, int n_in,
                              void* d_out, int out_size)
{
    const float* feat = (const float*)d_in[1];
    const float* anch = (const float*)d_in[2];
    const float* W1   = (const float*)d_in[3];
    const float* b1   = (const float*)d_in[4];
    const float* Wc   = (const float*)d_in[5];
    const float* bc   = (const float*)d_in[6];
    const float* Wr   = (const float*)d_in[7];
    const float* br   = (const float*)d_in[8];
    float* out = (float*)d_out;

    cudaFuncSetAttribute(conv_mma,     cudaFuncAttributeMaxDynamicSharedMemorySize, SMEM_TOT);
    cudaFuncSetAttribute(heads_kernel, cudaFuncAttributeMaxDynamicSharedMemorySize, 512*45*4);
    cudaFuncSetAttribute(sort_kernel,  cudaFuncAttributeMaxDynamicSharedMemorySize, CAND_CAP*8);
    cudaFuncSetAttribute(nms_sweep,    cudaFuncAttributeMaxDynamicSharedMemorySize, 96000 + POST_NMS*4);

    zero_kernel<<<64, 1024>>>();
    split_x<<<(NPIX*CIN + 255)/256, 256>>>(feat);
    split_w<<<dim3(KTOT/32, COC/32), dim3(32, 8)>>>(W1);
    conv_mma<<<148, 512, SMEM_TOT>>>(b1);
    heads_kernel<<<NPIX/64, 256, 512*45*4>>>(Wc, bc, Wr, br, anch,
                                             out, out + NROW);
    thresh_kernel<<<1, 1024>>>();
    compact_kernel<<<(NROW + 255)/256, 256>>>();
    sort_kernel<<<1, 1024, CAND_CAP*8>>>();
    nms_mask_kernel<<<dim3(NMSB, NMSB), 64>>>();
    nms_sweep<<<1, 1024, 96000 + POST_NMS*4>>>(out + NROW + NROW*4);
}